// round 1
// baseline (speedup 1.0000x reference)
#include <cuda_runtime.h>
#include <cuda_bf16.h>

#define NN 4096
#define CC 256
#define HH 8
#define DHH 32
#define EE 32768
#define FW 128            // 4096 bits / 32 = words per bitset row
#define C4 (4*CC)         // 1024

// ---------------- scratch (device globals; no runtime allocation) ----------
__device__ int      g_indeg[NN];
__device__ int      g_outdeg[NN];
__device__ int      g_spd[EE];
__device__ unsigned g_Fa[NN*FW];
__device__ unsigned g_Fb[NN*FW];
__device__ float    g_xin[NN*CC];
__device__ float    g_xn [NN*CC];
__device__ float    g_Q  [NN*CC];
__device__ float    g_K  [NN*CC];
__device__ float    g_V  [NN*CC];
__device__ float    g_msg[NN*CC];
__device__ float    g_h  [NN*CC];
__device__ float    g_hn [NN*CC];
__device__ float    g_ff1[NN*C4];
__device__ float    g_scoreE[EE*HH];
__device__ float    g_ssum[NN*HH];
__device__ unsigned g_mEnc[NN*HH];

// ---------------- degree count ---------------------------------------------
__global__ void deg_kernel(const int* __restrict__ ei) {
    int e = blockIdx.x * blockDim.x + threadIdx.x;
    if (e < EE) {
        atomicAdd(&g_outdeg[ei[e]], 1);
        atomicAdd(&g_indeg [ei[EE + e]], 1);
    }
}

// x_in = x + in_deg_emb[bucket(in)] + out_deg_emb[bucket(out)]
__global__ void xin_kernel(const float* __restrict__ x,
                           const float* __restrict__ ide,
                           const float* __restrict__ ode) {
    int n = blockIdx.x, c = threadIdx.x;
    int bi = min(31 - __clz(g_indeg [n] + 1), 8);
    int bo = min(31 - __clz(g_outdeg[n] + 1), 8);
    g_xin[n*CC + c] = x[n*CC + c] + ide[bi*CC + c] + ode[bo*CC + c];
}

// ---------------- SPD via bitset reachability -------------------------------
__global__ void ident_kernel() {
    int n = blockIdx.x * blockDim.x + threadIdx.x;
    if (n < NN) g_Fa[n*FW + (n >> 5)] = 1u << (n & 31);
}

__global__ void prop_kernel(const unsigned* __restrict__ F,
                            unsigned* __restrict__ Fn,
                            const int* __restrict__ ei) {
    int e = blockIdx.x;            // one block per edge, 128 threads = 128 words
    int w = threadIdx.x;
    int s = ei[e], d = ei[EE + e];
    unsigned v = F[s*FW + w];
    if (v) atomicOr(&Fn[d*FW + w], v);
}

__global__ void probe_kernel(const unsigned* __restrict__ F,
                             const int* __restrict__ ei, int k) {
    int e = blockIdx.x * blockDim.x + threadIdx.x;
    if (e < EE) {
        int s = ei[e], d = ei[EE + e];
        if (g_spd[e] == 0 && ((F[s*FW + (d >> 5)] >> (d & 31)) & 1u))
            g_spd[e] = k;
    }
}

// ---------------- LayerNorm (block per row, 256 threads) --------------------
__global__ void ln_kernel(const float* __restrict__ in,
                          const float* __restrict__ g,
                          const float* __restrict__ b,
                          float* __restrict__ out) {
    __shared__ float sh[16];
    int n = blockIdx.x, t = threadIdx.x;
    float v = in[n*CC + t];
    float s = v;
    #pragma unroll
    for (int o = 16; o; o >>= 1) s += __shfl_xor_sync(0xffffffffu, s, o);
    if ((t & 31) == 0) sh[t >> 5] = s;
    __syncthreads();
    if (t == 0) { float a = 0; for (int i = 0; i < 8; i++) a += sh[i]; sh[8] = a * (1.0f/CC); }
    __syncthreads();
    float mu = sh[8];
    float d  = v - mu;
    float q  = d * d;
    #pragma unroll
    for (int o = 16; o; o >>= 1) q += __shfl_xor_sync(0xffffffffu, q, o);
    if ((t & 31) == 0) sh[t >> 5] = q;
    __syncthreads();
    if (t == 0) { float a = 0; for (int i = 0; i < 8; i++) a += sh[i]; sh[9] = rsqrtf(a * (1.0f/CC) + 1e-5f); }
    __syncthreads();
    out[n*CC + t] = g[t] * d * sh[9] + b[t];
}

// ---------------- tiled fp32 GEMM: C = A[rows,K] @ B[K,M] + bias (+epilogue)
// mode 0: +bias; mode 1: +bias+resid; mode 2: gelu(+bias)
__global__ __launch_bounds__(256)
void gemm_kernel(const float* __restrict__ A, const float* __restrict__ B,
                 const float* __restrict__ bias, const float* __restrict__ resid,
                 float* __restrict__ Cout, int K, int M, int mode) {
    __shared__ float As[16][64];
    __shared__ float Bs[16][64];
    int tx = threadIdx.x, ty = threadIdx.y;
    int tid = ty * 16 + tx;
    int row0 = blockIdx.y * 64;
    int col0 = blockIdx.x * 64;
    float acc[4][4] = {};
    int ar = tid >> 2;          // 0..63 : A tile row
    int ac = (tid & 3) * 4;     // 0,4,8,12 : A tile k-col
    int br = tid >> 4;          // 0..15 : B tile k-row
    int bc = (tid & 15) * 4;    // 0..60 : B tile col
    for (int k0 = 0; k0 < K; k0 += 16) {
        float4 av = *(const float4*)&A[(row0 + ar) * K + k0 + ac];
        As[ac + 0][ar] = av.x; As[ac + 1][ar] = av.y;
        As[ac + 2][ar] = av.z; As[ac + 3][ar] = av.w;
        float4 bv = *(const float4*)&B[(k0 + br) * M + col0 + bc];
        *(float4*)&Bs[br][bc] = bv;
        __syncthreads();
        #pragma unroll
        for (int kk = 0; kk < 16; kk++) {
            float a[4], b[4];
            #pragma unroll
            for (int i = 0; i < 4; i++) a[i] = As[kk][ty*4 + i];
            #pragma unroll
            for (int j = 0; j < 4; j++) b[j] = Bs[kk][tx*4 + j];
            #pragma unroll
            for (int i = 0; i < 4; i++)
                #pragma unroll
                for (int j = 0; j < 4; j++) acc[i][j] += a[i] * b[j];
        }
        __syncthreads();
    }
    #pragma unroll
    for (int i = 0; i < 4; i++) {
        int r = row0 + ty*4 + i;
        #pragma unroll
        for (int j = 0; j < 4; j++) {
            int c = col0 + tx*4 + j;
            float v = acc[i][j] + bias[c];
            if (mode == 1)      v += resid[r*M + c];
            else if (mode == 2) v = 0.5f * v * (1.0f + erff(v * 0.70710678118654752f));
            Cout[r*M + c] = v;
        }
    }
}

// ---------------- edge attention --------------------------------------------
// scores + running segment max (encoded-unsigned atomicMax)
__global__ void score_kernel(const int* __restrict__ ei,
                             const float* __restrict__ spd_emb,
                             const float* __restrict__ et_bias) {
    int e = blockIdx.x;
    int t = threadIdx.x;       // 256 threads = 8 warps, warp h handles head h
    int h = t >> 5, l = t & 31;
    int s = ei[e], d = ei[EE + e];
    float qv = g_Q[d*CC + h*DHH + l];
    float kv = g_K[s*CC + h*DHH + l];
    float p = qv * kv;
    #pragma unroll
    for (int o = 16; o; o >>= 1) p += __shfl_xor_sync(0xffffffffu, p, o);
    if (l == 0) {
        int sp = g_spd[e]; if (sp == 0) sp = 4;   // unreachable -> MAX_SPD+1
        float sc = p * 0.17677669529663687f + spd_emb[sp*HH + h] + et_bias[0];
        g_scoreE[e*HH + h] = sc;
        unsigned u = __float_as_uint(sc);
        u = (u & 0x80000000u) ? ~u : (u | 0x80000000u);
        atomicMax(&g_mEnc[d*HH + h], u);
    }
}

__global__ void expsum_kernel(const int* __restrict__ ei) {
    int tid = blockIdx.x * blockDim.x + threadIdx.x;
    if (tid < EE * HH) {
        int e = tid >> 3, h = tid & 7;
        int d = ei[EE + e];
        unsigned u = g_mEnc[d*HH + h];
        float m = (u & 0x80000000u) ? __uint_as_float(u & 0x7FFFFFFFu)
                                    : __uint_as_float(~u);
        float ex = expf(g_scoreE[tid] - m);
        g_scoreE[tid] = ex;
        atomicAdd(&g_ssum[d*HH + h], ex);
    }
}

__global__ void msg_kernel(const int* __restrict__ ei) {
    int e = blockIdx.x;
    int t = threadIdx.x;        // 256 = H*DH
    int h = t >> 5;
    int s = ei[e], d = ei[EE + e];
    float sum = g_ssum[d*HH + h];
    float wn = g_scoreE[e*HH + h] / (sum > 0.0f ? sum : 1.0f);
    atomicAdd(&g_msg[d*CC + t], wn * g_V[s*CC + t]);
}

// ---------------- launch ----------------------------------------------------
extern "C" void kernel_launch(void* const* d_in, const int* in_sizes, int n_in,
                              void* d_out, int out_size) {
    const float* x      = (const float*)d_in[0];
    const int*   ei     = (const int*)  d_in[1];
    const float* Wq     = (const float*)d_in[2];
    const float* bq     = (const float*)d_in[3];
    const float* Wk     = (const float*)d_in[4];
    const float* bk     = (const float*)d_in[5];
    const float* Wv     = (const float*)d_in[6];
    const float* bv     = (const float*)d_in[7];
    const float* Wo     = (const float*)d_in[8];
    const float* bo     = (const float*)d_in[9];
    const float* W1     = (const float*)d_in[10];
    const float* b1     = (const float*)d_in[11];
    const float* W2     = (const float*)d_in[12];
    const float* b2     = (const float*)d_in[13];
    const float* g1     = (const float*)d_in[14];
    const float* beta1  = (const float*)d_in[15];
    const float* g2     = (const float*)d_in[16];
    const float* beta2  = (const float*)d_in[17];
    const float* spde   = (const float*)d_in[18];
    const float* ide    = (const float*)d_in[19];
    const float* ode    = (const float*)d_in[20];
    const float* etb    = (const float*)d_in[21];
    float* out = (float*)d_out;

    void *p_indeg, *p_outdeg, *p_spd, *p_Fa, *p_Fb, *p_msg, *p_ssum, *p_mEnc;
    float *pQ, *pK, *pV, *p_xin, *p_xn, *p_msgf, *p_h, *p_hn, *p_ff1;
    cudaGetSymbolAddress(&p_indeg,  g_indeg);
    cudaGetSymbolAddress(&p_outdeg, g_outdeg);
    cudaGetSymbolAddress(&p_spd,    g_spd);
    cudaGetSymbolAddress(&p_Fa,     g_Fa);
    cudaGetSymbolAddress(&p_Fb,     g_Fb);
    cudaGetSymbolAddress(&p_msg,    g_msg);
    cudaGetSymbolAddress(&p_ssum,   g_ssum);
    cudaGetSymbolAddress(&p_mEnc,   g_mEnc);
    cudaGetSymbolAddress((void**)&pQ,    g_Q);
    cudaGetSymbolAddress((void**)&pK,    g_K);
    cudaGetSymbolAddress((void**)&pV,    g_V);
    cudaGetSymbolAddress((void**)&p_xin, g_xin);
    cudaGetSymbolAddress((void**)&p_xn,  g_xn);
    cudaGetSymbolAddress((void**)&p_msgf,g_msg);
    cudaGetSymbolAddress((void**)&p_h,   g_h);
    cudaGetSymbolAddress((void**)&p_hn,  g_hn);
    cudaGetSymbolAddress((void**)&p_ff1, g_ff1);

    // reset per-replay state
    cudaMemsetAsync(p_indeg,  0, NN*sizeof(int));
    cudaMemsetAsync(p_outdeg, 0, NN*sizeof(int));
    cudaMemsetAsync(p_spd,    0, EE*sizeof(int));
    cudaMemsetAsync(p_Fa,     0, (size_t)NN*FW*sizeof(unsigned));
    cudaMemsetAsync(p_Fb,     0, (size_t)NN*FW*sizeof(unsigned));
    cudaMemsetAsync(p_msg,    0, (size_t)NN*CC*sizeof(float));
    cudaMemsetAsync(p_ssum,   0, NN*HH*sizeof(float));
    cudaMemsetAsync(p_mEnc,   0, NN*HH*sizeof(unsigned));

    // degrees + input embedding
    deg_kernel<<<EE/256, 256>>>(ei);
    xin_kernel<<<NN, CC>>>(x, ide, ode);

    // SPD: exact-length-k frontiers, ping-pong Fa/Fb
    ident_kernel<<<NN/256, 256>>>();
    unsigned *Fa = (unsigned*)p_Fa, *Fb = (unsigned*)p_Fb;
    // k = 1 : Fa -> Fb
    prop_kernel <<<EE, FW>>>(Fa, Fb, ei);
    probe_kernel<<<EE/256, 256>>>(Fb, ei, 1);
    cudaMemsetAsync(p_Fa, 0, (size_t)NN*FW*sizeof(unsigned));
    // k = 2 : Fb -> Fa
    prop_kernel <<<EE, FW>>>(Fb, Fa, ei);
    probe_kernel<<<EE/256, 256>>>(Fa, ei, 2);
    cudaMemsetAsync(p_Fb, 0, (size_t)NN*FW*sizeof(unsigned));
    // k = 3 : Fa -> Fb
    prop_kernel <<<EE, FW>>>(Fa, Fb, ei);
    probe_kernel<<<EE/256, 256>>>(Fb, ei, 3);

    // LN1 + QKV projections
    ln_kernel<<<NN, CC>>>(p_xin, g1, beta1, p_xn);
    dim3 blk(16, 16);
    dim3 grdC(CC/64, NN/64);      // 4 x 64
    gemm_kernel<<<grdC, blk>>>(p_xn, Wq, bq, nullptr, pQ, CC, CC, 0);
    gemm_kernel<<<grdC, blk>>>(p_xn, Wk, bk, nullptr, pK, CC, CC, 0);
    gemm_kernel<<<grdC, blk>>>(p_xn, Wv, bv, nullptr, pV, CC, CC, 0);

    // edge attention
    score_kernel <<<EE, 256>>>(ei, spde, etb);
    expsum_kernel<<<EE*HH/256, 256>>>(ei);
    msg_kernel   <<<EE, 256>>>(ei);

    // h = x_in + msg @ Wo + bo
    gemm_kernel<<<grdC, blk>>>(p_msgf, Wo, bo, p_xin, p_h, CC, CC, 1);

    // LN2 + FFN
    ln_kernel<<<NN, CC>>>(p_h, g2, beta2, p_hn);
    dim3 grdF1(C4/64, NN/64);     // 16 x 64
    gemm_kernel<<<grdF1, blk>>>(p_hn, W1, b1, nullptr, p_ff1, CC, C4, 2);
    gemm_kernel<<<grdC,  blk>>>(p_ff1, W2, b2, p_h, out, C4, CC, 1);
}

// round 3
// speedup vs baseline: 1.8074x; 1.8074x over previous
#include <cuda_runtime.h>
#include <cuda_bf16.h>

#define NN 4096
#define CC 256
#define HH 8
#define DHH 32
#define EE 32768
#define FW 128            // 4096 bits / 32 words per bitset row
#define C4 (4*CC)         // 1024

// ---------------- scratch (device globals; no runtime allocation) ----------
__device__ int      g_indeg[NN];
__device__ int      g_outdeg[NN];
__device__ int      g_spd[EE];
__device__ unsigned g_Fa[NN*FW];
__device__ unsigned g_Fb[NN*FW];
__device__ float    g_xin[NN*CC];
__device__ float    g_xn [NN*CC];
__device__ float    g_Q  [NN*CC];
__device__ float    g_K  [NN*CC];
__device__ float    g_V  [NN*CC];
__device__ float    g_msg[NN*CC];
__device__ float    g_h  [NN*CC];
__device__ float    g_hn [NN*CC];
__device__ float    g_ff1[NN*C4];
__device__ float    g_scoreE[EE*HH];
__device__ float    g_ssum[NN*HH];
__device__ unsigned g_mEnc[NN*HH];

// ---------------- degree count ---------------------------------------------
__global__ void deg_kernel(const int* __restrict__ ei) {
    int e = blockIdx.x * blockDim.x + threadIdx.x;
    if (e < EE) {
        atomicAdd(&g_outdeg[ei[e]], 1);
        atomicAdd(&g_indeg [ei[EE + e]], 1);
    }
}

__global__ void xin_kernel(const float* __restrict__ x,
                           const float* __restrict__ ide,
                           const float* __restrict__ ode) {
    int n = blockIdx.x, c = threadIdx.x;
    int bi = min(31 - __clz(g_indeg [n] + 1), 8);
    int bo = min(31 - __clz(g_outdeg[n] + 1), 8);
    g_xin[n*CC + c] = x[n*CC + c] + ide[bi*CC + c] + ode[bo*CC + c];
}

// ---------------- SPD via bitset reachability -------------------------------
// step 1 from identity frontier: F1[d] |= bit(s) -- one atomic per edge
__global__ void prop1_kernel(const int* __restrict__ ei, unsigned* __restrict__ Fn) {
    int e = blockIdx.x * blockDim.x + threadIdx.x;
    if (e < EE) {
        int s = ei[e], d = ei[EE + e];
        atomicOr(&Fn[d*FW + (s >> 5)], 1u << (s & 31));
    }
}

// steps 2,3: 32 threads per edge, uint4 per thread (4x MLP), 8 edges/block
__global__ __launch_bounds__(256)
void propv_kernel(const unsigned* __restrict__ F, unsigned* __restrict__ Fn,
                  const int* __restrict__ ei) {
    int grp = threadIdx.x >> 5, l = threadIdx.x & 31;
    int e = blockIdx.x * 8 + grp;
    int s = ei[e], d = ei[EE + e];
    uint4 v = *(const uint4*)&F[s*FW + l*4];
    unsigned* dst = &Fn[d*FW + l*4];
    if (v.x) atomicOr(dst + 0, v.x);
    if (v.y) atomicOr(dst + 1, v.y);
    if (v.z) atomicOr(dst + 2, v.z);
    if (v.w) atomicOr(dst + 3, v.w);
}

__global__ void probe_kernel(const unsigned* __restrict__ F,
                             const int* __restrict__ ei, int k) {
    int e = blockIdx.x * blockDim.x + threadIdx.x;
    if (e < EE) {
        int s = ei[e], d = ei[EE + e];
        if (g_spd[e] == 0 && ((F[s*FW + (d >> 5)] >> (d & 31)) & 1u))
            g_spd[e] = k;
    }
}

// ---------------- LayerNorm (block per row, 256 threads) --------------------
__global__ void ln_kernel(const float* __restrict__ in,
                          const float* __restrict__ g,
                          const float* __restrict__ b,
                          float* __restrict__ out) {
    __shared__ float sh[16];
    int n = blockIdx.x, t = threadIdx.x;
    float v = in[n*CC + t];
    float s = v;
    #pragma unroll
    for (int o = 16; o; o >>= 1) s += __shfl_xor_sync(0xffffffffu, s, o);
    if ((t & 31) == 0) sh[t >> 5] = s;
    __syncthreads();
    if (t == 0) { float a = 0; for (int i = 0; i < 8; i++) a += sh[i]; sh[8] = a * (1.0f/CC); }
    __syncthreads();
    float mu = sh[8];
    float d  = v - mu;
    float q  = d * d;
    #pragma unroll
    for (int o = 16; o; o >>= 1) q += __shfl_xor_sync(0xffffffffu, q, o);
    if ((t & 31) == 0) sh[t >> 5] = q;
    __syncthreads();
    if (t == 0) { float a = 0; for (int i = 0; i < 8; i++) a += sh[i]; sh[9] = rsqrtf(a * (1.0f/CC) + 1e-5f); }
    __syncthreads();
    out[n*CC + t] = g[t] * d * sh[9] + b[t];
}

// ---------------- tf32 tensor-core GEMM -------------------------------------
// C[M,N] = A[M,K] @ B[K,N] + bias (+ epilogue). Block tile 128x64x32,
// 8 warps in 4(M) x 2(N), warp tile 32x32 = 2x4 mma.m16n8k8 tiles.
// mode 0: +bias; 1: +bias+resid; 2: gelu(+bias)
__device__ __forceinline__ float to_tf32(float x) {
    unsigned u;
    asm("cvt.rna.tf32.f32 %0, %1;" : "=r"(u) : "f"(x));
    return __uint_as_float(u);
}

#define GTM 128
#define GTN 64
#define GTK 32

__global__ __launch_bounds__(256)
void gemm_tf32(const float* __restrict__ A, const float* __restrict__ B,
               const float* __restrict__ bias, const float* __restrict__ resid,
               float* __restrict__ C, int K, int N, int mode) {
    __shared__ float As[GTM][GTK + 4];
    __shared__ float Bs[GTK][GTN + 4];
    int tid  = threadIdx.x;
    int wid  = tid >> 5, lane = tid & 31;
    int warpM = wid & 3, warpN = wid >> 2;
    int lm = lane >> 2, lk = lane & 3;
    int m0 = blockIdx.y * GTM;
    int n0 = blockIdx.x * GTN;

    float c[2][4][4];
    #pragma unroll
    for (int i = 0; i < 2; i++)
        #pragma unroll
        for (int j = 0; j < 4; j++)
            #pragma unroll
            for (int q = 0; q < 4; q++) c[i][j][q] = 0.0f;

    int ar = tid >> 3;            // 0..31
    int ak = (tid & 7) * 4;       // 0..28
    int bk = tid >> 4;            // 0..15
    int bn = (tid & 15) * 4;      // 0..60

    for (int k0 = 0; k0 < K; k0 += GTK) {
        #pragma unroll
        for (int p = 0; p < 4; p++) {
            int row = ar + p * 32;
            float4 v = *(const float4*)&A[(size_t)(m0 + row) * K + k0 + ak];
            v.x = to_tf32(v.x); v.y = to_tf32(v.y);
            v.z = to_tf32(v.z); v.w = to_tf32(v.w);
            *(float4*)&As[row][ak] = v;
        }
        #pragma unroll
        for (int p = 0; p < 2; p++) {
            int kr = bk + p * 16;
            float4 v = *(const float4*)&B[(size_t)(k0 + kr) * N + n0 + bn];
            v.x = to_tf32(v.x); v.y = to_tf32(v.y);
            v.z = to_tf32(v.z); v.w = to_tf32(v.w);
            *(float4*)&Bs[kr][bn] = v;
        }
        __syncthreads();
        #pragma unroll
        for (int k8 = 0; k8 < GTK; k8 += 8) {
            unsigned a[2][4], b[4][2];
            #pragma unroll
            for (int i = 0; i < 2; i++) {
                int r = warpM * 32 + i * 16 + lm;
                a[i][0] = __float_as_uint(As[r    ][k8 + lk    ]);
                a[i][1] = __float_as_uint(As[r + 8][k8 + lk    ]);
                a[i][2] = __float_as_uint(As[r    ][k8 + lk + 4]);
                a[i][3] = __float_as_uint(As[r + 8][k8 + lk + 4]);
            }
            #pragma unroll
            for (int j = 0; j < 4; j++) {
                int cn = warpN * 32 + j * 8 + lm;
                b[j][0] = __float_as_uint(Bs[k8 + lk    ][cn]);
                b[j][1] = __float_as_uint(Bs[k8 + lk + 4][cn]);
            }
            #pragma unroll
            for (int i = 0; i < 2; i++)
                #pragma unroll
                for (int j = 0; j < 4; j++) {
                    asm volatile(
                        "mma.sync.aligned.m16n8k8.row.col.f32.tf32.tf32.f32 "
                        "{%0,%1,%2,%3}, {%4,%5,%6,%7}, {%8,%9}, {%0,%1,%2,%3};"
                        : "+f"(c[i][j][0]), "+f"(c[i][j][1]),
                          "+f"(c[i][j][2]), "+f"(c[i][j][3])
                        : "r"(a[i][0]), "r"(a[i][1]), "r"(a[i][2]), "r"(a[i][3]),
                          "r"(b[j][0]), "r"(b[j][1]));
                }
        }
        __syncthreads();
    }

    #pragma unroll
    for (int i = 0; i < 2; i++) {
        #pragma unroll
        for (int j = 0; j < 4; j++) {
            int r  = m0 + warpM * 32 + i * 16 + lm;
            int cn = n0 + warpN * 32 + j * 8 + 2 * lk;
            float b0 = bias[cn], b1 = bias[cn + 1];
            #pragma unroll
            for (int half = 0; half < 2; half++) {
                int rr = r + half * 8;
                float v0 = c[i][j][half * 2 + 0] + b0;
                float v1 = c[i][j][half * 2 + 1] + b1;
                if (mode == 1) {
                    v0 += resid[(size_t)rr * N + cn];
                    v1 += resid[(size_t)rr * N + cn + 1];
                } else if (mode == 2) {
                    v0 = 0.5f * v0 * (1.0f + erff(v0 * 0.70710678118654752f));
                    v1 = 0.5f * v1 * (1.0f + erff(v1 * 0.70710678118654752f));
                }
                *(float2*)&C[(size_t)rr * N + cn] = make_float2(v0, v1);
            }
        }
    }
}

// ---------------- edge attention --------------------------------------------
__global__ void score_kernel(const int* __restrict__ ei,
                             const float* __restrict__ spd_emb,
                             const float* __restrict__ et_bias) {
    int e = blockIdx.x;
    int t = threadIdx.x;       // 8 warps, warp h handles head h
    int h = t >> 5, l = t & 31;
    int s = ei[e], d = ei[EE + e];
    float qv = g_Q[d*CC + h*DHH + l];
    float kv = g_K[s*CC + h*DHH + l];
    float p = qv * kv;
    #pragma unroll
    for (int o = 16; o; o >>= 1) p += __shfl_xor_sync(0xffffffffu, p, o);
    if (l == 0) {
        int sp = g_spd[e]; if (sp == 0) sp = 4;
        float sc = p * 0.17677669529663687f + spd_emb[sp*HH + h] + et_bias[0];
        g_scoreE[e*HH + h] = sc;
        unsigned u = __float_as_uint(sc);
        u = (u & 0x80000000u) ? ~u : (u | 0x80000000u);
        atomicMax(&g_mEnc[d*HH + h], u);
    }
}

__global__ void expsum_kernel(const int* __restrict__ ei) {
    int tid = blockIdx.x * blockDim.x + threadIdx.x;
    if (tid < EE * HH) {
        int e = tid >> 3, h = tid & 7;
        int d = ei[EE + e];
        unsigned u = g_mEnc[d*HH + h];
        float m = (u & 0x80000000u) ? __uint_as_float(u & 0x7FFFFFFFu)
                                    : __uint_as_float(~u);
        float ex = expf(g_scoreE[tid] - m);
        g_scoreE[tid] = ex;
        atomicAdd(&g_ssum[d*HH + h], ex);
    }
}

// 4 edges per block, 64 threads/edge, float4 vectorized reduction
__global__ __launch_bounds__(256)
void msg_kernel(const int* __restrict__ ei) {
    int sub = threadIdx.x >> 6;   // 0..3
    int t   = threadIdx.x & 63;   // 0..63
    int e = blockIdx.x * 4 + sub;
    int s = ei[e], d = ei[EE + e];
    int h = t >> 3;
    float sum = g_ssum[d*HH + h];
    float wn = g_scoreE[e*HH + h] / (sum > 0.0f ? sum : 1.0f);
    float4 v = *(const float4*)&g_V[s*CC + t*4];
    asm volatile("red.global.add.v4.f32 [%0], {%1,%2,%3,%4};"
                 :: "l"(&g_msg[d*CC + t*4]),
                    "f"(wn*v.x), "f"(wn*v.y), "f"(wn*v.z), "f"(wn*v.w)
                 : "memory");
}

// ---------------- launch ----------------------------------------------------
extern "C" void kernel_launch(void* const* d_in, const int* in_sizes, int n_in,
                              void* d_out, int out_size) {
    const float* x      = (const float*)d_in[0];
    const int*   ei     = (const int*)  d_in[1];
    const float* Wq     = (const float*)d_in[2];
    const float* bq     = (const float*)d_in[3];
    const float* Wk     = (const float*)d_in[4];
    const float* bk     = (const float*)d_in[5];
    const float* Wv     = (const float*)d_in[6];
    const float* bv     = (const float*)d_in[7];
    const float* Wo     = (const float*)d_in[8];
    const float* bo     = (const float*)d_in[9];
    const float* W1     = (const float*)d_in[10];
    const float* b1     = (const float*)d_in[11];
    const float* W2     = (const float*)d_in[12];
    const float* b2     = (const float*)d_in[13];
    const float* g1     = (const float*)d_in[14];
    const float* beta1  = (const float*)d_in[15];
    const float* g2     = (const float*)d_in[16];
    const float* beta2  = (const float*)d_in[17];
    const float* spde   = (const float*)d_in[18];
    const float* ide    = (const float*)d_in[19];
    const float* ode    = (const float*)d_in[20];
    const float* etb    = (const float*)d_in[21];
    float* out = (float*)d_out;

    void *p_indeg, *p_outdeg, *p_spd, *p_Fa, *p_Fb, *p_ssum, *p_mEnc;
    float *pQ, *pK, *pV, *p_xin, *p_xn, *p_msgf, *p_h, *p_hn, *p_ff1;
    cudaGetSymbolAddress(&p_indeg,  g_indeg);
    cudaGetSymbolAddress(&p_outdeg, g_outdeg);
    cudaGetSymbolAddress(&p_spd,    g_spd);
    cudaGetSymbolAddress(&p_Fa,     g_Fa);
    cudaGetSymbolAddress(&p_Fb,     g_Fb);
    cudaGetSymbolAddress(&p_ssum,   g_ssum);
    cudaGetSymbolAddress(&p_mEnc,   g_mEnc);
    cudaGetSymbolAddress((void**)&pQ,    g_Q);
    cudaGetSymbolAddress((void**)&pK,    g_K);
    cudaGetSymbolAddress((void**)&pV,    g_V);
    cudaGetSymbolAddress((void**)&p_xin, g_xin);
    cudaGetSymbolAddress((void**)&p_xn,  g_xn);
    cudaGetSymbolAddress((void**)&p_msgf,g_msg);
    cudaGetSymbolAddress((void**)&p_h,   g_h);
    cudaGetSymbolAddress((void**)&p_hn,  g_hn);
    cudaGetSymbolAddress((void**)&p_ff1, g_ff1);

    // reset per-replay state
    cudaMemsetAsync(p_indeg,  0, NN*sizeof(int));
    cudaMemsetAsync(p_outdeg, 0, NN*sizeof(int));
    cudaMemsetAsync(p_spd,    0, EE*sizeof(int));
    cudaMemsetAsync(p_Fa,     0, (size_t)NN*FW*sizeof(unsigned));
    cudaMemsetAsync(p_Fb,     0, (size_t)NN*FW*sizeof(unsigned));
    cudaMemsetAsync(p_msgf,   0, (size_t)NN*CC*sizeof(float));
    cudaMemsetAsync(p_ssum,   0, NN*HH*sizeof(float));
    cudaMemsetAsync(p_mEnc,   0, NN*HH*sizeof(unsigned));

    // degrees + input embedding
    deg_kernel<<<EE/256, 256>>>(ei);
    xin_kernel<<<NN, CC>>>(x, ide, ode);

    // SPD: exact-length-k frontiers, ping-pong Fb/Fa
    unsigned *Fa = (unsigned*)p_Fa, *Fb = (unsigned*)p_Fb;
    // k = 1 : identity -> Fb (single atomic per edge)
    prop1_kernel<<<EE/256, 256>>>(ei, Fb);
    probe_kernel<<<EE/256, 256>>>(Fb, ei, 1);
    // k = 2 : Fb -> Fa
    propv_kernel<<<EE/8, 256>>>(Fb, Fa, ei);
    probe_kernel<<<EE/256, 256>>>(Fa, ei, 2);
    cudaMemsetAsync(p_Fb, 0, (size_t)NN*FW*sizeof(unsigned));
    // k = 3 : Fa -> Fb
    propv_kernel<<<EE/8, 256>>>(Fa, Fb, ei);
    probe_kernel<<<EE/256, 256>>>(Fb, ei, 3);

    // LN1 + QKV projections
    ln_kernel<<<NN, CC>>>(p_xin, g1, beta1, p_xn);
    dim3 blk(256);
    dim3 grdC(CC/GTN, NN/GTM);       // 4 x 32
    gemm_tf32<<<grdC, blk>>>(p_xn, Wq, bq, nullptr, pQ, CC, CC, 0);
    gemm_tf32<<<grdC, blk>>>(p_xn, Wk, bk, nullptr, pK, CC, CC, 0);
    gemm_tf32<<<grdC, blk>>>(p_xn, Wv, bv, nullptr, pV, CC, CC, 0);

    // edge attention
    score_kernel <<<EE, 256>>>(ei, spde, etb);
    expsum_kernel<<<EE*HH/256, 256>>>(ei);
    msg_kernel   <<<EE/4, 256>>>(ei);

    // h = x_in + msg @ Wo + bo
    gemm_tf32<<<grdC, blk>>>(p_msgf, Wo, bo, p_xin, p_h, CC, CC, 1);

    // LN2 + FFN
    ln_kernel<<<NN, CC>>>(p_h, g2, beta2, p_hn);
    dim3 grdF1(C4/GTN, NN/GTM);      // 16 x 32
    gemm_tf32<<<grdF1, blk>>>(p_hn, W1, b1, nullptr, p_ff1, CC, C4, 2);
    gemm_tf32<<<grdC,  blk>>>(p_ff1, W2, b2, p_h, out, C4, CC, 1);
}

// round 5
// speedup vs baseline: 2.1408x; 1.1845x over previous
#include <cuda_runtime.h>
#include <cuda_bf16.h>

#define NN 4096
#define CC 256
#define HH 8
#define DHH 32
#define EE 32768
#define FW 128            // 4096 bits / 32 words per bitset row
#define C4 (4*CC)         // 1024

// ---------------- scratch (device globals; no runtime allocation) ----------
__device__ int      g_indeg[NN];
__device__ int      g_outdeg[NN];
__device__ int      g_spd[EE];
__device__ unsigned g_Fa[NN*FW];
__device__ unsigned g_Fb[NN*FW];
__device__ int      g_off[NN + 1];
__device__ int      g_cur[NN];
__device__ int      g_elist[EE];     // packed (src<<17)|e, ordered by dst
__device__ float    g_xin[NN*CC];
__device__ float    g_xn [NN*CC];
__device__ float    g_Q  [NN*CC];
__device__ float    g_K  [NN*CC];
__device__ float    g_V  [NN*CC];
__device__ float    g_msg[NN*CC];
__device__ float    g_h  [NN*CC];
__device__ float    g_hn [NN*CC];
__device__ float    g_ff1[NN*C4];

// ---------------- degree count ---------------------------------------------
__global__ void deg_kernel(const int* __restrict__ ei) {
    int e = blockIdx.x * blockDim.x + threadIdx.x;
    if (e < EE) {
        atomicAdd(&g_outdeg[ei[e]], 1);
        atomicAdd(&g_indeg [ei[EE + e]], 1);
    }
}

__global__ void xin_kernel(const float* __restrict__ x,
                           const float* __restrict__ ide,
                           const float* __restrict__ ode) {
    int n = blockIdx.x, c = threadIdx.x;
    int bi = min(31 - __clz(g_indeg [n] + 1), 8);
    int bo = min(31 - __clz(g_outdeg[n] + 1), 8);
    g_xin[n*CC + c] = x[n*CC + c] + ide[bi*CC + c] + ode[bo*CC + c];
}

// ---------------- CSR build: exclusive scan of indeg (1 block, 1024 thr) ---
__global__ __launch_bounds__(1024) void scan_kernel() {
    __shared__ int wsum[32];
    int t = threadIdx.x;
    int v0 = g_indeg[4*t+0], v1 = g_indeg[4*t+1];
    int v2 = g_indeg[4*t+2], v3 = g_indeg[4*t+3];
    int s = v0 + v1 + v2 + v3;
    int lane = t & 31, w = t >> 5;
    int x = s;
    #pragma unroll
    for (int o = 1; o < 32; o <<= 1) {
        int y = __shfl_up_sync(0xffffffffu, x, o);
        if (lane >= o) x += y;
    }
    if (lane == 31) wsum[w] = x;
    __syncthreads();
    if (w == 0) {
        int y = wsum[lane];
        #pragma unroll
        for (int o = 1; o < 32; o <<= 1) {
            int z = __shfl_up_sync(0xffffffffu, y, o);
            if (lane >= o) y += z;
        }
        wsum[lane] = y;
    }
    __syncthreads();
    int base = (w > 0 ? wsum[w-1] : 0) + (x - s);  // exclusive prefix
    int o0 = base, o1 = o0 + v0, o2 = o1 + v1, o3 = o2 + v2;
    g_off[4*t+0] = o0; g_cur[4*t+0] = o0;
    g_off[4*t+1] = o1; g_cur[4*t+1] = o1;
    g_off[4*t+2] = o2; g_cur[4*t+2] = o2;
    g_off[4*t+3] = o3; g_cur[4*t+3] = o3;
    if (t == 1023) g_off[NN] = o3 + v3;
}

__global__ void fill_kernel(const int* __restrict__ ei) {
    int e = blockIdx.x * blockDim.x + threadIdx.x;
    if (e < EE) {
        int s = ei[e], d = ei[EE + e];
        int pos = atomicAdd(&g_cur[d], 1);
        g_elist[pos] = (s << 17) | e;
    }
}

// ---------------- SPD via bitset reachability -------------------------------
__global__ void prop1_kernel(const int* __restrict__ ei, unsigned* __restrict__ Fn) {
    int e = blockIdx.x * blockDim.x + threadIdx.x;
    if (e < EE) {
        int s = ei[e], d = ei[EE + e];
        atomicOr(&Fn[d*FW + (s >> 5)], 1u << (s & 31));
    }
}

// probe step k against F, propagate F -> Fn (step k+1). 8 edges/block.
__global__ __launch_bounds__(256)
void propv_probe_kernel(const unsigned* __restrict__ F, unsigned* __restrict__ Fn,
                        const int* __restrict__ ei, int k) {
    int grp = threadIdx.x >> 5, l = threadIdx.x & 31;
    int e = blockIdx.x * 8 + grp;
    int s = ei[e], d = ei[EE + e];
    uint4 v = *(const uint4*)&F[s*FW + l*4];
    unsigned* dst = &Fn[d*FW + l*4];
    if (v.x) atomicOr(dst + 0, v.x);
    if (v.y) atomicOr(dst + 1, v.y);
    if (v.z) atomicOr(dst + 2, v.z);
    if (v.w) atomicOr(dst + 3, v.w);
    if (l == 0 && g_spd[e] == 0 &&
        ((F[s*FW + (d >> 5)] >> (d & 31)) & 1u))
        g_spd[e] = k;
}

__global__ void probe_kernel(const unsigned* __restrict__ F,
                             const int* __restrict__ ei, int k) {
    int e = blockIdx.x * blockDim.x + threadIdx.x;
    if (e < EE) {
        int s = ei[e], d = ei[EE + e];
        if (g_spd[e] == 0 && ((F[s*FW + (d >> 5)] >> (d & 31)) & 1u))
            g_spd[e] = k;
    }
}

// ---------------- LayerNorm (block per row, 256 threads) --------------------
__global__ void ln_kernel(const float* __restrict__ in,
                          const float* __restrict__ g,
                          const float* __restrict__ b,
                          float* __restrict__ out) {
    __shared__ float sh[16];
    int n = blockIdx.x, t = threadIdx.x;
    float v = in[n*CC + t];
    float s = v;
    #pragma unroll
    for (int o = 16; o; o >>= 1) s += __shfl_xor_sync(0xffffffffu, s, o);
    if ((t & 31) == 0) sh[t >> 5] = s;
    __syncthreads();
    if (t == 0) { float a = 0; for (int i = 0; i < 8; i++) a += sh[i]; sh[8] = a * (1.0f/CC); }
    __syncthreads();
    float mu = sh[8];
    float d  = v - mu;
    float q  = d * d;
    #pragma unroll
    for (int o = 16; o; o >>= 1) q += __shfl_xor_sync(0xffffffffu, q, o);
    if ((t & 31) == 0) sh[t >> 5] = q;
    __syncthreads();
    if (t == 0) { float a = 0; for (int i = 0; i < 8; i++) a += sh[i]; sh[9] = rsqrtf(a * (1.0f/CC) + 1e-5f); }
    __syncthreads();
    out[n*CC + t] = g[t] * d * sh[9] + b[t];
}

// ---------------- tf32 tensor-core GEMM core --------------------------------
__device__ __forceinline__ float to_tf32(float x) {
    unsigned u;
    asm("cvt.rna.tf32.f32 %0, %1;" : "=r"(u) : "f"(x));
    return __uint_as_float(u);
}

#define GTM 128
#define GTN 64
#define GTK 32

__device__ __forceinline__
void gemm_core(const float* __restrict__ A, const float* __restrict__ B,
               const float* __restrict__ bias, const float* __restrict__ resid,
               float* __restrict__ C, int K, int N, int mode,
               int m0, int n0) {
    __shared__ float As[GTM][GTK + 4];
    __shared__ float Bs[GTK][GTN + 4];
    int tid  = threadIdx.x;
    int wid  = tid >> 5, lane = tid & 31;
    int warpM = wid & 3, warpN = wid >> 2;
    int lm = lane >> 2, lk = lane & 3;

    float c[2][4][4];
    #pragma unroll
    for (int i = 0; i < 2; i++)
        #pragma unroll
        for (int j = 0; j < 4; j++)
            #pragma unroll
            for (int q = 0; q < 4; q++) c[i][j][q] = 0.0f;

    int ar = tid >> 3;
    int ak = (tid & 7) * 4;
    int bk = tid >> 4;
    int bn = (tid & 15) * 4;

    for (int k0 = 0; k0 < K; k0 += GTK) {
        #pragma unroll
        for (int p = 0; p < 4; p++) {
            int row = ar + p * 32;
            float4 v = *(const float4*)&A[(size_t)(m0 + row) * K + k0 + ak];
            v.x = to_tf32(v.x); v.y = to_tf32(v.y);
            v.z = to_tf32(v.z); v.w = to_tf32(v.w);
            *(float4*)&As[row][ak] = v;
        }
        #pragma unroll
        for (int p = 0; p < 2; p++) {
            int kr = bk + p * 16;
            float4 v = *(const float4*)&B[(size_t)(k0 + kr) * N + n0 + bn];
            v.x = to_tf32(v.x); v.y = to_tf32(v.y);
            v.z = to_tf32(v.z); v.w = to_tf32(v.w);
            *(float4*)&Bs[kr][bn] = v;
        }
        __syncthreads();
        #pragma unroll
        for (int k8 = 0; k8 < GTK; k8 += 8) {
            unsigned a[2][4], b[4][2];
            #pragma unroll
            for (int i = 0; i < 2; i++) {
                int r = warpM * 32 + i * 16 + lm;
                a[i][0] = __float_as_uint(As[r    ][k8 + lk    ]);
                a[i][1] = __float_as_uint(As[r + 8][k8 + lk    ]);
                a[i][2] = __float_as_uint(As[r    ][k8 + lk + 4]);
                a[i][3] = __float_as_uint(As[r + 8][k8 + lk + 4]);
            }
            #pragma unroll
            for (int j = 0; j < 4; j++) {
                int cn = warpN * 32 + j * 8 + lm;
                b[j][0] = __float_as_uint(Bs[k8 + lk    ][cn]);
                b[j][1] = __float_as_uint(Bs[k8 + lk + 4][cn]);
            }
            #pragma unroll
            for (int i = 0; i < 2; i++)
                #pragma unroll
                for (int j = 0; j < 4; j++) {
                    asm volatile(
                        "mma.sync.aligned.m16n8k8.row.col.f32.tf32.tf32.f32 "
                        "{%0,%1,%2,%3}, {%4,%5,%6,%7}, {%8,%9}, {%0,%1,%2,%3};"
                        : "+f"(c[i][j][0]), "+f"(c[i][j][1]),
                          "+f"(c[i][j][2]), "+f"(c[i][j][3])
                        : "r"(a[i][0]), "r"(a[i][1]), "r"(a[i][2]), "r"(a[i][3]),
                          "r"(b[j][0]), "r"(b[j][1]));
                }
        }
        __syncthreads();
    }

    #pragma unroll
    for (int i = 0; i < 2; i++) {
        #pragma unroll
        for (int j = 0; j < 4; j++) {
            int r  = m0 + warpM * 32 + i * 16 + lm;
            int cn = n0 + warpN * 32 + j * 8 + 2 * lk;
            float b0 = bias[cn], b1 = bias[cn + 1];
            #pragma unroll
            for (int half = 0; half < 2; half++) {
                int rr = r + half * 8;
                float v0 = c[i][j][half * 2 + 0] + b0;
                float v1 = c[i][j][half * 2 + 1] + b1;
                if (mode == 1) {
                    v0 += resid[(size_t)rr * N + cn];
                    v1 += resid[(size_t)rr * N + cn + 1];
                } else if (mode == 2) {
                    v0 = 0.5f * v0 * (1.0f + erff(v0 * 0.70710678118654752f));
                    v1 = 0.5f * v1 * (1.0f + erff(v1 * 0.70710678118654752f));
                }
                *(float2*)&C[(size_t)rr * N + cn] = make_float2(v0, v1);
            }
        }
    }
}

__global__ __launch_bounds__(256)
void gemm_tf32(const float* __restrict__ A, const float* __restrict__ B,
               const float* __restrict__ bias, const float* __restrict__ resid,
               float* __restrict__ C, int K, int N, int mode) {
    gemm_core(A, B, bias, resid, C, K, N, mode,
              blockIdx.y * GTM, blockIdx.x * GTN);
}

// fused QKV: blockIdx.z selects weight/bias/output
__global__ __launch_bounds__(256)
void gemm_qkv(const float* __restrict__ A,
              const float* __restrict__ Wq, const float* __restrict__ bq,
              const float* __restrict__ Wk, const float* __restrict__ bk,
              const float* __restrict__ Wv, const float* __restrict__ bv,
              float* __restrict__ Q, float* __restrict__ K,
              float* __restrict__ V) {
    int z = blockIdx.z;
    const float* B    = (z == 0) ? Wq : (z == 1) ? Wk : Wv;
    const float* bias = (z == 0) ? bq : (z == 1) ? bk : bv;
    float*       C    = (z == 0) ? Q  : (z == 1) ? K  : V;
    gemm_core(A, B, bias, nullptr, C, CC, CC, 0,
              blockIdx.y * GTM, blockIdx.x * GTN);
}

// ---------------- fused single-pass edge attention ---------------------------
// block = dst node; 8 warps = 8 heads; lane = dim within head.
// Softmax computed without max-subtraction (shift-invariant; scores bounded).
__global__ __launch_bounds__(256)
void attn_kernel(const float* __restrict__ spde,
                 const float* __restrict__ etb) {
    int d = blockIdx.x;
    int t = threadIdx.x, h = t >> 5, l = t & 31;
    int beg = g_off[d], end = g_off[d + 1];
    float q  = g_Q[d*CC + t];
    float et = etb[0];
    float sum = 0.0f, acc = 0.0f;
    for (int i = beg; i < end; i++) {
        int pk = g_elist[i];
        int e = pk & 0x1FFFF;
        int s = pk >> 17;
        float kv = g_K[s*CC + t];
        float p = q * kv;
        #pragma unroll
        for (int o = 16; o; o >>= 1) p += __shfl_xor_sync(0xffffffffu, p, o);
        int sp = g_spd[e]; if (sp == 0) sp = 4;
        float ex = expf(p * 0.17677669529663687f + spde[sp*HH + h] + et);
        sum += ex;
        acc += ex * g_V[s*CC + t];
    }
    float inv = (sum > 0.0f) ? (1.0f / sum) : 0.0f;
    g_msg[d*CC + t] = acc * inv;
}

// ---------------- launch ----------------------------------------------------
extern "C" void kernel_launch(void* const* d_in, const int* in_sizes, int n_in,
                              void* d_out, int out_size) {
    const float* x      = (const float*)d_in[0];
    const int*   ei     = (const int*)  d_in[1];
    const float* Wq     = (const float*)d_in[2];
    const float* bq     = (const float*)d_in[3];
    const float* Wk     = (const float*)d_in[4];
    const float* bk     = (const float*)d_in[5];
    const float* Wv     = (const float*)d_in[6];
    const float* bv     = (const float*)d_in[7];
    const float* Wo     = (const float*)d_in[8];
    const float* bo     = (const float*)d_in[9];
    const float* W1     = (const float*)d_in[10];
    const float* b1     = (const float*)d_in[11];
    const float* W2     = (const float*)d_in[12];
    const float* b2     = (const float*)d_in[13];
    const float* g1     = (const float*)d_in[14];
    const float* beta1  = (const float*)d_in[15];
    const float* g2     = (const float*)d_in[16];
    const float* beta2  = (const float*)d_in[17];
    const float* spde   = (const float*)d_in[18];
    const float* ide    = (const float*)d_in[19];
    const float* ode    = (const float*)d_in[20];
    const float* etb    = (const float*)d_in[21];
    float* out = (float*)d_out;

    void *p_indeg, *p_outdeg, *p_spd, *p_Fa, *p_Fb;
    float *pQ, *pK, *pV, *p_xin, *p_xn, *p_msgf, *p_h, *p_hn, *p_ff1;
    cudaGetSymbolAddress(&p_indeg,  g_indeg);
    cudaGetSymbolAddress(&p_outdeg, g_outdeg);
    cudaGetSymbolAddress(&p_spd,    g_spd);
    cudaGetSymbolAddress(&p_Fa,     g_Fa);
    cudaGetSymbolAddress(&p_Fb,     g_Fb);
    cudaGetSymbolAddress((void**)&pQ,    g_Q);
    cudaGetSymbolAddress((void**)&pK,    g_K);
    cudaGetSymbolAddress((void**)&pV,    g_V);
    cudaGetSymbolAddress((void**)&p_xin, g_xin);
    cudaGetSymbolAddress((void**)&p_xn,  g_xn);
    cudaGetSymbolAddress((void**)&p_msgf,g_msg);
    cudaGetSymbolAddress((void**)&p_h,   g_h);
    cudaGetSymbolAddress((void**)&p_hn,  g_hn);
    cudaGetSymbolAddress((void**)&p_ff1, g_ff1);

    // reset per-replay state
    cudaMemsetAsync(p_indeg,  0, NN*sizeof(int));
    cudaMemsetAsync(p_outdeg, 0, NN*sizeof(int));
    cudaMemsetAsync(p_spd,    0, EE*sizeof(int));
    cudaMemsetAsync(p_Fa,     0, (size_t)NN*FW*sizeof(unsigned));
    cudaMemsetAsync(p_Fb,     0, (size_t)NN*FW*sizeof(unsigned));

    // degrees + input embedding + CSR build
    deg_kernel<<<EE/256, 256>>>(ei);
    xin_kernel<<<NN, CC>>>(x, ide, ode);
    scan_kernel<<<1, 1024>>>();
    fill_kernel<<<EE/256, 256>>>(ei);

    // SPD: exact-length-k frontiers, probe fused into next propagation
    unsigned *Fa = (unsigned*)p_Fa, *Fb = (unsigned*)p_Fb;
    prop1_kernel<<<EE/256, 256>>>(ei, Fb);                    // identity -> Fb (k=1)
    propv_probe_kernel<<<EE/8, 256>>>(Fb, Fa, ei, 1);         // probe k=1, Fb -> Fa
    cudaMemsetAsync(p_Fb, 0, (size_t)NN*FW*sizeof(unsigned));
    propv_probe_kernel<<<EE/8, 256>>>(Fa, Fb, ei, 2);         // probe k=2, Fa -> Fb
    probe_kernel<<<EE/256, 256>>>(Fb, ei, 3);                 // probe k=3

    // LN1 + fused QKV projection
    ln_kernel<<<NN, CC>>>(p_xin, g1, beta1, p_xn);
    dim3 blk(256);
    dim3 grdQKV(CC/GTN, NN/GTM, 3);  // 4 x 32 x 3
    gemm_qkv<<<grdQKV, blk>>>(p_xn, Wq, bq, Wk, bk, Wv, bv, pQ, pK, pV);

    // fused edge attention (CSR gather, no atomics)
    attn_kernel<<<NN, 256>>>(spde, etb);

    // h = x_in + msg @ Wo + bo
    dim3 grdC(CC/GTN, NN/GTM);       // 4 x 32
    gemm_tf32<<<grdC, blk>>>(p_msgf, Wo, bo, p_xin, p_h, CC, CC, 1);

    // LN2 + FFN
    ln_kernel<<<NN, CC>>>(p_h, g2, beta2, p_hn);
    dim3 grdF1(C4/GTN, NN/GTM);      // 16 x 32
    gemm_tf32<<<grdF1, blk>>>(p_hn, W1, b1, nullptr, p_ff1, CC, C4, 2);
    gemm_tf32<<<grdC,  blk>>>(p_ff1, W2, b2, p_h, out, C4, CC, 1);
}

// round 7
// speedup vs baseline: 2.2030x; 1.0290x over previous
#include <cuda_runtime.h>
#include <cuda_bf16.h>

#define NN 4096
#define CC 256
#define HH 8
#define DHH 32
#define EE 32768
#define FW 128            // 4096 bits / 32 words per bitset row
#define C4 (4*CC)         // 1024

// ---------------- zeroed scratch: ONE block, ONE memset ---------------------
#define OFF_INDEG  0
#define OFF_OUTDEG (OFF_INDEG  + NN)
#define OFF_SPD    (OFF_OUTDEG + NN)
#define OFF_F1     (OFF_SPD    + EE)
#define OFF_F2     (OFF_F1     + NN*FW)
#define OFF_F3     (OFF_F2     + NN*FW)
#define ZTOT       (OFF_F3     + NN*FW)
__device__ unsigned g_zblk[ZTOT];

#define G_INDEG  ((int*)(g_zblk + OFF_INDEG))
#define G_OUTDEG ((int*)(g_zblk + OFF_OUTDEG))
#define G_SPD    ((int*)(g_zblk + OFF_SPD))
#define G_F1     (g_zblk + OFF_F1)
#define G_F2     (g_zblk + OFF_F2)
#define G_F3     (g_zblk + OFF_F3)

// ---------------- other scratch (overwritten, no zeroing needed) ------------
__device__ int      g_off[NN + 1];
__device__ int      g_cur[NN];
__device__ int      g_elist[EE];     // packed (src<<17)|e, ordered by dst
__device__ float    g_xin[NN*CC];
__device__ float    g_xn [NN*CC];
__device__ float    g_Q  [NN*CC];
__device__ float    g_K  [NN*CC];
__device__ float    g_V  [NN*CC];
__device__ float    g_msg[NN*CC];
__device__ float    g_h  [NN*CC];
__device__ float    g_hn [NN*CC];
__device__ float    g_ff1[NN*C4];

// ---------------- degrees + SPD step-1 (merged edge pass) -------------------
__global__ void deg_prop1_kernel(const int* __restrict__ ei) {
    int e = blockIdx.x * blockDim.x + threadIdx.x;
    if (e < EE) {
        int s = ei[e], d = ei[EE + e];
        atomicAdd(&G_OUTDEG[s], 1);
        atomicAdd(&G_INDEG [d], 1);
        atomicOr(&G_F1[d*FW + (s >> 5)], 1u << (s & 31));
    }
}

// ---------------- CSR build: exclusive scan of indeg (1 block, 1024 thr) ---
__global__ __launch_bounds__(1024) void scan_kernel() {
    __shared__ int wsum[32];
    int t = threadIdx.x;
    int v0 = G_INDEG[4*t+0], v1 = G_INDEG[4*t+1];
    int v2 = G_INDEG[4*t+2], v3 = G_INDEG[4*t+3];
    int s = v0 + v1 + v2 + v3;
    int lane = t & 31, w = t >> 5;
    int x = s;
    #pragma unroll
    for (int o = 1; o < 32; o <<= 1) {
        int y = __shfl_up_sync(0xffffffffu, x, o);
        if (lane >= o) x += y;
    }
    if (lane == 31) wsum[w] = x;
    __syncthreads();
    if (w == 0) {
        int y = wsum[lane];
        #pragma unroll
        for (int o = 1; o < 32; o <<= 1) {
            int z = __shfl_up_sync(0xffffffffu, y, o);
            if (lane >= o) y += z;
        }
        wsum[lane] = y;
    }
    __syncthreads();
    int base = (w > 0 ? wsum[w-1] : 0) + (x - s);  // exclusive prefix
    int o0 = base, o1 = o0 + v0, o2 = o1 + v1, o3 = o2 + v2;
    g_off[4*t+0] = o0; g_cur[4*t+0] = o0;
    g_off[4*t+1] = o1; g_cur[4*t+1] = o1;
    g_off[4*t+2] = o2; g_cur[4*t+2] = o2;
    g_off[4*t+3] = o3; g_cur[4*t+3] = o3;
    if (t == 1023) g_off[NN] = o3 + v3;
}

__global__ void fill_kernel(const int* __restrict__ ei) {
    int e = blockIdx.x * blockDim.x + threadIdx.x;
    if (e < EE) {
        int s = ei[e], d = ei[EE + e];
        int pos = atomicAdd(&g_cur[d], 1);
        g_elist[pos] = (s << 17) | e;
    }
}

// ---------------- SPD: probe step k against F, propagate F -> Fn ------------
__global__ __launch_bounds__(256)
void propv_probe_kernel(const unsigned* __restrict__ F, unsigned* __restrict__ Fn,
                        const int* __restrict__ ei, int k) {
    int grp = threadIdx.x >> 5, l = threadIdx.x & 31;
    int e = blockIdx.x * 8 + grp;
    int s = ei[e], d = ei[EE + e];
    uint4 v = *(const uint4*)&F[s*FW + l*4];
    unsigned* dst = &Fn[d*FW + l*4];
    if (v.x) atomicOr(dst + 0, v.x);
    if (v.y) atomicOr(dst + 1, v.y);
    if (v.z) atomicOr(dst + 2, v.z);
    if (v.w) atomicOr(dst + 3, v.w);
    if (l == 0 && G_SPD[e] == 0 &&
        ((F[s*FW + (d >> 5)] >> (d & 31)) & 1u))
        G_SPD[e] = k;
}

// ---------------- fused xin + LayerNorm1 (block per row, 256 threads) -------
__global__ void xin_ln_kernel(const float* __restrict__ x,
                              const float* __restrict__ ide,
                              const float* __restrict__ ode,
                              const float* __restrict__ g,
                              const float* __restrict__ b) {
    __shared__ float sh[16];
    int n = blockIdx.x, t = threadIdx.x;
    int bi = min(31 - __clz(G_INDEG [n] + 1), 8);
    int bo = min(31 - __clz(G_OUTDEG[n] + 1), 8);
    float v = x[n*CC + t] + ide[bi*CC + t] + ode[bo*CC + t];
    g_xin[n*CC + t] = v;
    float s = v;
    #pragma unroll
    for (int o = 16; o; o >>= 1) s += __shfl_xor_sync(0xffffffffu, s, o);
    if ((t & 31) == 0) sh[t >> 5] = s;
    __syncthreads();
    if (t == 0) { float a = 0; for (int i = 0; i < 8; i++) a += sh[i]; sh[8] = a * (1.0f/CC); }
    __syncthreads();
    float mu = sh[8];
    float d  = v - mu;
    float q  = d * d;
    #pragma unroll
    for (int o = 16; o; o >>= 1) q += __shfl_xor_sync(0xffffffffu, q, o);
    if ((t & 31) == 0) sh[t >> 5] = q;
    __syncthreads();
    if (t == 0) { float a = 0; for (int i = 0; i < 8; i++) a += sh[i]; sh[9] = rsqrtf(a * (1.0f/CC) + 1e-5f); }
    __syncthreads();
    g_xn[n*CC + t] = g[t] * d * sh[9] + b[t];
}

// ---------------- plain LayerNorm (block per row, 256 threads) --------------
__global__ void ln_kernel(const float* __restrict__ in,
                          const float* __restrict__ g,
                          const float* __restrict__ b,
                          float* __restrict__ out) {
    __shared__ float sh[16];
    int n = blockIdx.x, t = threadIdx.x;
    float v = in[n*CC + t];
    float s = v;
    #pragma unroll
    for (int o = 16; o; o >>= 1) s += __shfl_xor_sync(0xffffffffu, s, o);
    if ((t & 31) == 0) sh[t >> 5] = s;
    __syncthreads();
    if (t == 0) { float a = 0; for (int i = 0; i < 8; i++) a += sh[i]; sh[8] = a * (1.0f/CC); }
    __syncthreads();
    float mu = sh[8];
    float d  = v - mu;
    float q  = d * d;
    #pragma unroll
    for (int o = 16; o; o >>= 1) q += __shfl_xor_sync(0xffffffffu, q, o);
    if ((t & 31) == 0) sh[t >> 5] = q;
    __syncthreads();
    if (t == 0) { float a = 0; for (int i = 0; i < 8; i++) a += sh[i]; sh[9] = rsqrtf(a * (1.0f/CC) + 1e-5f); }
    __syncthreads();
    out[n*CC + t] = g[t] * d * sh[9] + b[t];
}

// ---------------- tf32 tensor-core GEMM core --------------------------------
__device__ __forceinline__ float to_tf32(float x) {
    unsigned u;
    asm("cvt.rna.tf32.f32 %0, %1;" : "=r"(u) : "f"(x));
    return __uint_as_float(u);
}

#define GTM 128
#define GTN 64
#define GTK 32

__device__ __forceinline__
void gemm_core(const float* __restrict__ A, const float* __restrict__ B,
               const float* __restrict__ bias, const float* __restrict__ resid,
               float* __restrict__ C, int K, int N, int mode,
               int m0, int n0) {
    __shared__ float As[GTM][GTK + 4];
    __shared__ float Bs[GTK][GTN + 4];
    int tid  = threadIdx.x;
    int wid  = tid >> 5, lane = tid & 31;
    int warpM = wid & 3, warpN = wid >> 2;
    int lm = lane >> 2, lk = lane & 3;

    float c[2][4][4];
    #pragma unroll
    for (int i = 0; i < 2; i++)
        #pragma unroll
        for (int j = 0; j < 4; j++)
            #pragma unroll
            for (int q = 0; q < 4; q++) c[i][j][q] = 0.0f;

    int ar = tid >> 3;
    int ak = (tid & 7) * 4;
    int bk = tid >> 4;
    int bn = (tid & 15) * 4;

    for (int k0 = 0; k0 < K; k0 += GTK) {
        #pragma unroll
        for (int p = 0; p < 4; p++) {
            int row = ar + p * 32;
            float4 v = *(const float4*)&A[(size_t)(m0 + row) * K + k0 + ak];
            v.x = to_tf32(v.x); v.y = to_tf32(v.y);
            v.z = to_tf32(v.z); v.w = to_tf32(v.w);
            *(float4*)&As[row][ak] = v;
        }
        #pragma unroll
        for (int p = 0; p < 2; p++) {
            int kr = bk + p * 16;
            float4 v = *(const float4*)&B[(size_t)(k0 + kr) * N + n0 + bn];
            v.x = to_tf32(v.x); v.y = to_tf32(v.y);
            v.z = to_tf32(v.z); v.w = to_tf32(v.w);
            *(float4*)&Bs[kr][bn] = v;
        }
        __syncthreads();
        #pragma unroll
        for (int k8 = 0; k8 < GTK; k8 += 8) {
            unsigned a[2][4], b[4][2];
            #pragma unroll
            for (int i = 0; i < 2; i++) {
                int r = warpM * 32 + i * 16 + lm;
                a[i][0] = __float_as_uint(As[r    ][k8 + lk    ]);
                a[i][1] = __float_as_uint(As[r + 8][k8 + lk    ]);
                a[i][2] = __float_as_uint(As[r    ][k8 + lk + 4]);
                a[i][3] = __float_as_uint(As[r + 8][k8 + lk + 4]);
            }
            #pragma unroll
            for (int j = 0; j < 4; j++) {
                int cn = warpN * 32 + j * 8 + lm;
                b[j][0] = __float_as_uint(Bs[k8 + lk    ][cn]);
                b[j][1] = __float_as_uint(Bs[k8 + lk + 4][cn]);
            }
            #pragma unroll
            for (int i = 0; i < 2; i++)
                #pragma unroll
                for (int j = 0; j < 4; j++) {
                    asm volatile(
                        "mma.sync.aligned.m16n8k8.row.col.f32.tf32.tf32.f32 "
                        "{%0,%1,%2,%3}, {%4,%5,%6,%7}, {%8,%9}, {%0,%1,%2,%3};"
                        : "+f"(c[i][j][0]), "+f"(c[i][j][1]),
                          "+f"(c[i][j][2]), "+f"(c[i][j][3])
                        : "r"(a[i][0]), "r"(a[i][1]), "r"(a[i][2]), "r"(a[i][3]),
                          "r"(b[j][0]), "r"(b[j][1]));
                }
        }
        __syncthreads();
    }

    #pragma unroll
    for (int i = 0; i < 2; i++) {
        #pragma unroll
        for (int j = 0; j < 4; j++) {
            int r  = m0 + warpM * 32 + i * 16 + lm;
            int cn = n0 + warpN * 32 + j * 8 + 2 * lk;
            float b0 = bias[cn], b1 = bias[cn + 1];
            #pragma unroll
            for (int half = 0; half < 2; half++) {
                int rr = r + half * 8;
                float v0 = c[i][j][half * 2 + 0] + b0;
                float v1 = c[i][j][half * 2 + 1] + b1;
                if (mode == 1) {
                    v0 += resid[(size_t)rr * N + cn];
                    v1 += resid[(size_t)rr * N + cn + 1];
                } else if (mode == 2) {
                    v0 = 0.5f * v0 * (1.0f + erff(v0 * 0.70710678118654752f));
                    v1 = 0.5f * v1 * (1.0f + erff(v1 * 0.70710678118654752f));
                }
                *(float2*)&C[(size_t)rr * N + cn] = make_float2(v0, v1);
            }
        }
    }
}

__global__ __launch_bounds__(256)
void gemm_tf32(const float* __restrict__ A, const float* __restrict__ B,
               const float* __restrict__ bias, const float* __restrict__ resid,
               float* __restrict__ C, int K, int N, int mode) {
    gemm_core(A, B, bias, resid, C, K, N, mode,
              blockIdx.y * GTM, blockIdx.x * GTN);
}

// fused QKV: blockIdx.z selects weight/bias/output
__global__ __launch_bounds__(256)
void gemm_qkv(const float* __restrict__ A,
              const float* __restrict__ Wq, const float* __restrict__ bq,
              const float* __restrict__ Wk, const float* __restrict__ bk,
              const float* __restrict__ Wv, const float* __restrict__ bv,
              float* __restrict__ Q, float* __restrict__ K,
              float* __restrict__ V) {
    int z = blockIdx.z;
    const float* B    = (z == 0) ? Wq : (z == 1) ? Wk : Wv;
    const float* bias = (z == 0) ? bq : (z == 1) ? bk : bv;
    float*       C    = (z == 0) ? Q  : (z == 1) ? K  : V;
    gemm_core(A, B, bias, nullptr, C, CC, CC, 0,
              blockIdx.y * GTM, blockIdx.x * GTN);
}

// ---------------- fused single-pass edge attention (+probe k=3 inline) ------
// block = dst node; 8 warps = 8 heads; lane = dim within head.
__global__ __launch_bounds__(256)
void attn_kernel(const float* __restrict__ spde,
                 const float* __restrict__ etb) {
    int d = blockIdx.x;
    int t = threadIdx.x, h = t >> 5;
    int beg = g_off[d], end = g_off[d + 1];
    float q  = g_Q[d*CC + t];
    float et = etb[0];
    float sum = 0.0f, acc = 0.0f;
    for (int i = beg; i < end; i++) {
        int pk = g_elist[i];
        int e = pk & 0x1FFFF;
        int s = pk >> 17;
        float kv = g_K[s*CC + t];
        float p = q * kv;
        #pragma unroll
        for (int o = 16; o; o >>= 1) p += __shfl_xor_sync(0xffffffffu, p, o);
        int sp = G_SPD[e];
        if (sp == 0)   // probe k=3 inline against F3; else unreachable -> 4
            sp = ((G_F3[s*FW + (d >> 5)] >> (d & 31)) & 1u) ? 3 : 4;
        float ex = expf(p * 0.17677669529663687f + spde[sp*HH + h] + et);
        sum += ex;
        acc += ex * g_V[s*CC + t];
    }
    float inv = (sum > 0.0f) ? (1.0f / sum) : 0.0f;
    g_msg[d*CC + t] = acc * inv;
}

// ---------------- launch ----------------------------------------------------
extern "C" void kernel_launch(void* const* d_in, const int* in_sizes, int n_in,
                              void* d_out, int out_size) {
    const float* x      = (const float*)d_in[0];
    const int*   ei     = (const int*)  d_in[1];
    const float* Wq     = (const float*)d_in[2];
    const float* bq     = (const float*)d_in[3];
    const float* Wk     = (const float*)d_in[4];
    const float* bk     = (const float*)d_in[5];
    const float* Wv     = (const float*)d_in[6];
    const float* bv     = (const float*)d_in[7];
    const float* Wo     = (const float*)d_in[8];
    const float* bo     = (const float*)d_in[9];
    const float* W1     = (const float*)d_in[10];
    const float* b1     = (const float*)d_in[11];
    const float* W2     = (const float*)d_in[12];
    const float* b2     = (const float*)d_in[13];
    const float* g1     = (const float*)d_in[14];
    const float* beta1  = (const float*)d_in[15];
    const float* g2     = (const float*)d_in[16];
    const float* beta2  = (const float*)d_in[17];
    const float* spde   = (const float*)d_in[18];
    const float* ide    = (const float*)d_in[19];
    const float* ode    = (const float*)d_in[20];
    const float* etb    = (const float*)d_in[21];
    float* out = (float*)d_out;

    void* p_zblk;
    float *pQ, *pK, *pV, *p_xn, *p_xin, *p_msgf, *p_h, *p_hn, *p_ff1;
    cudaGetSymbolAddress(&p_zblk, g_zblk);
    cudaGetSymbolAddress((void**)&pQ,    g_Q);
    cudaGetSymbolAddress((void**)&pK,    g_K);
    cudaGetSymbolAddress((void**)&pV,    g_V);
    cudaGetSymbolAddress((void**)&p_xin, g_xin);
    cudaGetSymbolAddress((void**)&p_xn,  g_xn);
    cudaGetSymbolAddress((void**)&p_msgf,g_msg);
    cudaGetSymbolAddress((void**)&p_h,   g_h);
    cudaGetSymbolAddress((void**)&p_hn,  g_hn);
    cudaGetSymbolAddress((void**)&p_ff1, g_ff1);

    unsigned* zb = (unsigned*)p_zblk;
    unsigned* F1 = zb + OFF_F1;
    unsigned* F2 = zb + OFF_F2;
    unsigned* F3 = zb + OFF_F3;

    // ONE reset for all per-replay state
    cudaMemsetAsync(p_zblk, 0, (size_t)ZTOT * sizeof(unsigned));

    // degrees + SPD step-1 in one edge pass; CSR build
    deg_prop1_kernel<<<EE/256, 256>>>(ei);
    scan_kernel<<<1, 1024>>>();
    fill_kernel<<<EE/256, 256>>>(ei);

    // SPD: probe k fused into propagation k+1; k=3 probed inside attn
    propv_probe_kernel<<<EE/8, 256>>>(F1, F2, ei, 1);
    propv_probe_kernel<<<EE/8, 256>>>(F2, F3, ei, 2);

    // fused xin + LN1, then fused QKV projection
    xin_ln_kernel<<<NN, CC>>>(x, ide, ode, g1, beta1);
    dim3 blk(256);
    dim3 grdQKV(CC/GTN, NN/GTM, 3);  // 4 x 32 x 3
    gemm_qkv<<<grdQKV, blk>>>(p_xn, Wq, bq, Wk, bk, Wv, bv, pQ, pK, pV);

    // fused edge attention (CSR gather, no atomics, probe3 inline)
    attn_kernel<<<NN, 256>>>(spde, etb);

    // h = x_in + msg @ Wo + bo
    dim3 grdC(CC/GTN, NN/GTM);       // 4 x 32
    gemm_tf32<<<grdC, blk>>>(p_msgf, Wo, bo, p_xin, p_h, CC, CC, 1);

    // LN2 + FFN
    ln_kernel<<<NN, CC>>>(p_h, g2, beta2, p_hn);
    dim3 grdF1(C4/GTN, NN/GTM);      // 16 x 32
    gemm_tf32<<<grdF1, blk>>>(p_hn, W1, b1, nullptr, p_ff1, CC, C4, 2);
    gemm_tf32<<<grdC,  blk>>>(p_ff1, W2, b2, p_h, out, C4, CC, 1);
}

// round 8
// speedup vs baseline: 2.4901x; 1.1303x over previous
#include <cuda_runtime.h>
#include <cuda_bf16.h>

#define NN 4096
#define CC 256
#define HH 8
#define DHH 32
#define EE 32768
#define FW 128            // 4096 bits / 32 words per bitset row
#define C4 (4*CC)         // 1024

// ---------------- zeroed scratch: ONE block, ONE memset ---------------------
#define OFF_INDEG  0
#define OFF_OUTDEG (OFF_INDEG  + NN)
#define OFF_SPD    (OFF_OUTDEG + NN)
#define OFF_F1     (OFF_SPD    + EE)
#define ZTOT       (OFF_F1     + NN*FW)
__device__ unsigned g_zblk[ZTOT];

#define G_INDEG  ((int*)(g_zblk + OFF_INDEG))
#define G_OUTDEG ((int*)(g_zblk + OFF_OUTDEG))
#define G_SPD    ((int*)(g_zblk + OFF_SPD))
#define G_F1     (g_zblk + OFF_F1)

// ---------------- other scratch (fully overwritten, no zeroing) -------------
__device__ unsigned g_F2[NN*FW];
__device__ unsigned g_F3[NN*FW];
__device__ int      g_off[NN + 1];
__device__ int      g_cur[NN];
__device__ int      g_elist[EE];     // packed (src<<17)|e, ordered by dst
__device__ float    g_xin[NN*CC];
__device__ float    g_xn [NN*CC];
__device__ float    g_Q  [NN*CC];
__device__ float    g_K  [NN*CC];
__device__ float    g_V  [NN*CC];
__device__ float    g_msg[NN*CC];
__device__ float    g_h  [NN*CC];
__device__ float    g_hn [NN*CC];
__device__ float    g_ff1[NN*C4];

// ---------------- degrees + SPD step-1 (merged edge pass) -------------------
__global__ void deg_prop1_kernel(const int* __restrict__ ei) {
    int e = blockIdx.x * blockDim.x + threadIdx.x;
    if (e < EE) {
        int s = ei[e], d = ei[EE + e];
        atomicAdd(&G_OUTDEG[s], 1);
        atomicAdd(&G_INDEG [d], 1);
        atomicOr(&G_F1[d*FW + (s >> 5)], 1u << (s & 31));
    }
}

// ---------------- CSR build: exclusive scan of indeg (1 block, 1024 thr) ---
__global__ __launch_bounds__(1024) void scan_kernel() {
    __shared__ int wsum[32];
    int t = threadIdx.x;
    int v0 = G_INDEG[4*t+0], v1 = G_INDEG[4*t+1];
    int v2 = G_INDEG[4*t+2], v3 = G_INDEG[4*t+3];
    int s = v0 + v1 + v2 + v3;
    int lane = t & 31, w = t >> 5;
    int x = s;
    #pragma unroll
    for (int o = 1; o < 32; o <<= 1) {
        int y = __shfl_up_sync(0xffffffffu, x, o);
        if (lane >= o) x += y;
    }
    if (lane == 31) wsum[w] = x;
    __syncthreads();
    if (w == 0) {
        int y = wsum[lane];
        #pragma unroll
        for (int o = 1; o < 32; o <<= 1) {
            int z = __shfl_up_sync(0xffffffffu, y, o);
            if (lane >= o) y += z;
        }
        wsum[lane] = y;
    }
    __syncthreads();
    int base = (w > 0 ? wsum[w-1] : 0) + (x - s);  // exclusive prefix
    int o0 = base, o1 = o0 + v0, o2 = o1 + v1, o3 = o2 + v2;
    g_off[4*t+0] = o0; g_cur[4*t+0] = o0;
    g_off[4*t+1] = o1; g_cur[4*t+1] = o1;
    g_off[4*t+2] = o2; g_cur[4*t+2] = o2;
    g_off[4*t+3] = o3; g_cur[4*t+3] = o3;
    if (t == 1023) g_off[NN] = o3 + v3;
}

__global__ void fill_kernel(const int* __restrict__ ei) {
    int e = blockIdx.x * blockDim.x + threadIdx.x;
    if (e < EE) {
        int s = ei[e], d = ei[EE + e];
        int pos = atomicAdd(&g_cur[d], 1);
        g_elist[pos] = (s << 17) | e;
    }
}

// ---------------- SPD: CSR gather propagation + inline probe ---------------
// block = dst node, thread w = bitset word. Fn[d][w] = OR over in-nbrs F[s][w].
// No atomics; Fn fully written so needs no pre-zeroing. Probe step k inline.
__global__ __launch_bounds__(128)
void prop_gather_kernel(const unsigned* __restrict__ F,
                        unsigned* __restrict__ Fn, int k) {
    int d = blockIdx.x, w = threadIdx.x;
    int beg = g_off[d], end = g_off[d + 1];
    unsigned acc = 0;
    for (int i = beg; i < end; i++) {
        int s = g_elist[i] >> 17;
        acc |= F[s*FW + w];
    }
    Fn[d*FW + w] = acc;
    // probe step k for this dst's in-edges
    for (int i = beg + w; i < end; i += 128) {
        int pk = g_elist[i];
        int e = pk & 0x1FFFF, s = pk >> 17;
        if (G_SPD[e] == 0 && ((F[s*FW + (d >> 5)] >> (d & 31)) & 1u))
            G_SPD[e] = k;
    }
}

// ---------------- fused xin + LayerNorm1 (block per row, 256 threads) -------
__global__ void xin_ln_kernel(const float* __restrict__ x,
                              const float* __restrict__ ide,
                              const float* __restrict__ ode,
                              const float* __restrict__ g,
                              const float* __restrict__ b) {
    __shared__ float sh[16];
    int n = blockIdx.x, t = threadIdx.x;
    int bi = min(31 - __clz(G_INDEG [n] + 1), 8);
    int bo = min(31 - __clz(G_OUTDEG[n] + 1), 8);
    float v = x[n*CC + t] + ide[bi*CC + t] + ode[bo*CC + t];
    g_xin[n*CC + t] = v;
    float s = v;
    #pragma unroll
    for (int o = 16; o; o >>= 1) s += __shfl_xor_sync(0xffffffffu, s, o);
    if ((t & 31) == 0) sh[t >> 5] = s;
    __syncthreads();
    if (t == 0) { float a = 0; for (int i = 0; i < 8; i++) a += sh[i]; sh[8] = a * (1.0f/CC); }
    __syncthreads();
    float mu = sh[8];
    float d  = v - mu;
    float q  = d * d;
    #pragma unroll
    for (int o = 16; o; o >>= 1) q += __shfl_xor_sync(0xffffffffu, q, o);
    if ((t & 31) == 0) sh[t >> 5] = q;
    __syncthreads();
    if (t == 0) { float a = 0; for (int i = 0; i < 8; i++) a += sh[i]; sh[9] = rsqrtf(a * (1.0f/CC) + 1e-5f); }
    __syncthreads();
    g_xn[n*CC + t] = g[t] * d * sh[9] + b[t];
}

// ---------------- plain LayerNorm (block per row, 256 threads) --------------
__global__ void ln_kernel(const float* __restrict__ in,
                          const float* __restrict__ g,
                          const float* __restrict__ b,
                          float* __restrict__ out) {
    __shared__ float sh[16];
    int n = blockIdx.x, t = threadIdx.x;
    float v = in[n*CC + t];
    float s = v;
    #pragma unroll
    for (int o = 16; o; o >>= 1) s += __shfl_xor_sync(0xffffffffu, s, o);
    if ((t & 31) == 0) sh[t >> 5] = s;
    __syncthreads();
    if (t == 0) { float a = 0; for (int i = 0; i < 8; i++) a += sh[i]; sh[8] = a * (1.0f/CC); }
    __syncthreads();
    float mu = sh[8];
    float d  = v - mu;
    float q  = d * d;
    #pragma unroll
    for (int o = 16; o; o >>= 1) q += __shfl_xor_sync(0xffffffffu, q, o);
    if ((t & 31) == 0) sh[t >> 5] = q;
    __syncthreads();
    if (t == 0) { float a = 0; for (int i = 0; i < 8; i++) a += sh[i]; sh[9] = rsqrtf(a * (1.0f/CC) + 1e-5f); }
    __syncthreads();
    out[n*CC + t] = g[t] * d * sh[9] + b[t];
}

// ---------------- tf32 tensor-core GEMM, cp.async double-buffered -----------
__device__ __forceinline__ unsigned to_tf32_u(float x) {
    unsigned u;
    asm("cvt.rna.tf32.f32 %0, %1;" : "=r"(u) : "f"(x));
    return u;
}

#define GTM 64
#define GTN 64
#define GTK 32

// block tile 64x64x32, 2-stage cp.async pipeline, 8 warps = 2(M) x 4(N),
// warp tile 32x16 = 2x2 mma.m16n8k8 tiles.
__device__ __forceinline__
void gemm_core(const float* __restrict__ A, const float* __restrict__ B,
               const float* __restrict__ bias, const float* __restrict__ resid,
               float* __restrict__ C, int K, int N, int mode,
               int m0, int n0) {
    __shared__ float As[2][GTM][GTK + 4];
    __shared__ float Bs[2][GTK][GTN + 4];
    int tid  = threadIdx.x;
    int wid  = tid >> 5, lane = tid & 31;
    int warpM = wid & 1, warpN = wid >> 1;
    int lm = lane >> 2, lk = lane & 3;

    float c[2][2][4];
    #pragma unroll
    for (int i = 0; i < 2; i++)
        #pragma unroll
        for (int j = 0; j < 2; j++)
            #pragma unroll
            for (int q = 0; q < 4; q++) c[i][j][q] = 0.0f;

    int ar = tid >> 3;            // 0..31 (2 rounds cover 64 rows)
    int ak = (tid & 7) * 4;       // 0..28
    int bk = tid >> 4;            // 0..15 (2 rounds cover 32 k-rows)
    int bn = (tid & 15) * 4;      // 0..60

    // prefetch tile k0 into stage buf
    auto prefetch = [&](int buf, int k0) {
        #pragma unroll
        for (int p = 0; p < 2; p++) {
            int row = ar + p * 32;
            unsigned dst = (unsigned)__cvta_generic_to_shared(&As[buf][row][ak]);
            asm volatile("cp.async.cg.shared.global [%0], [%1], 16;"
                         :: "r"(dst), "l"(&A[(size_t)(m0 + row) * K + k0 + ak]));
        }
        #pragma unroll
        for (int p = 0; p < 2; p++) {
            int kr = bk + p * 16;
            unsigned dst = (unsigned)__cvta_generic_to_shared(&Bs[buf][kr][bn]);
            asm volatile("cp.async.cg.shared.global [%0], [%1], 16;"
                         :: "r"(dst), "l"(&B[(size_t)(k0 + kr) * N + n0 + bn]));
        }
        asm volatile("cp.async.commit_group;");
    };

    prefetch(0, 0);
    int buf = 0;
    for (int k0 = 0; k0 < K; k0 += GTK, buf ^= 1) {
        if (k0 + GTK < K) {
            prefetch(buf ^ 1, k0 + GTK);
            asm volatile("cp.async.wait_group 1;");
        } else {
            asm volatile("cp.async.wait_group 0;");
        }
        __syncthreads();
        #pragma unroll
        for (int k8 = 0; k8 < GTK; k8 += 8) {
            unsigned a[2][4], b[2][2];
            #pragma unroll
            for (int i = 0; i < 2; i++) {
                int r = warpM * 32 + i * 16 + lm;
                a[i][0] = to_tf32_u(As[buf][r    ][k8 + lk    ]);
                a[i][1] = to_tf32_u(As[buf][r + 8][k8 + lk    ]);
                a[i][2] = to_tf32_u(As[buf][r    ][k8 + lk + 4]);
                a[i][3] = to_tf32_u(As[buf][r + 8][k8 + lk + 4]);
            }
            #pragma unroll
            for (int j = 0; j < 2; j++) {
                int cn = warpN * 16 + j * 8 + lm;
                b[j][0] = to_tf32_u(Bs[buf][k8 + lk    ][cn]);
                b[j][1] = to_tf32_u(Bs[buf][k8 + lk + 4][cn]);
            }
            #pragma unroll
            for (int i = 0; i < 2; i++)
                #pragma unroll
                for (int j = 0; j < 2; j++) {
                    asm volatile(
                        "mma.sync.aligned.m16n8k8.row.col.f32.tf32.tf32.f32 "
                        "{%0,%1,%2,%3}, {%4,%5,%6,%7}, {%8,%9}, {%0,%1,%2,%3};"
                        : "+f"(c[i][j][0]), "+f"(c[i][j][1]),
                          "+f"(c[i][j][2]), "+f"(c[i][j][3])
                        : "r"(a[i][0]), "r"(a[i][1]), "r"(a[i][2]), "r"(a[i][3]),
                          "r"(b[j][0]), "r"(b[j][1]));
                }
        }
        __syncthreads();
    }

    #pragma unroll
    for (int i = 0; i < 2; i++) {
        #pragma unroll
        for (int j = 0; j < 2; j++) {
            int r  = m0 + warpM * 32 + i * 16 + lm;
            int cn = n0 + warpN * 16 + j * 8 + 2 * lk;
            float b0 = bias[cn], b1 = bias[cn + 1];
            #pragma unroll
            for (int half = 0; half < 2; half++) {
                int rr = r + half * 8;
                float v0 = c[i][j][half * 2 + 0] + b0;
                float v1 = c[i][j][half * 2 + 1] + b1;
                if (mode == 1) {
                    v0 += resid[(size_t)rr * N + cn];
                    v1 += resid[(size_t)rr * N + cn + 1];
                } else if (mode == 2) {
                    v0 = 0.5f * v0 * (1.0f + erff(v0 * 0.70710678118654752f));
                    v1 = 0.5f * v1 * (1.0f + erff(v1 * 0.70710678118654752f));
                }
                *(float2*)&C[(size_t)rr * N + cn] = make_float2(v0, v1);
            }
        }
    }
}

__global__ __launch_bounds__(256)
void gemm_tf32(const float* __restrict__ A, const float* __restrict__ B,
               const float* __restrict__ bias, const float* __restrict__ resid,
               float* __restrict__ C, int K, int N, int mode) {
    gemm_core(A, B, bias, resid, C, K, N, mode,
              blockIdx.y * GTM, blockIdx.x * GTN);
}

// fused QKV: blockIdx.z selects weight/bias/output
__global__ __launch_bounds__(256)
void gemm_qkv(const float* __restrict__ A,
              const float* __restrict__ Wq, const float* __restrict__ bq,
              const float* __restrict__ Wk, const float* __restrict__ bk,
              const float* __restrict__ Wv, const float* __restrict__ bv,
              float* __restrict__ Q, float* __restrict__ K,
              float* __restrict__ V) {
    int z = blockIdx.z;
    const float* B    = (z == 0) ? Wq : (z == 1) ? Wk : Wv;
    const float* bias = (z == 0) ? bq : (z == 1) ? bk : bv;
    float*       C    = (z == 0) ? Q  : (z == 1) ? K  : V;
    gemm_core(A, B, bias, nullptr, C, CC, CC, 0,
              blockIdx.y * GTM, blockIdx.x * GTN);
}

// ---------------- fused single-pass edge attention (+probe k=3 inline) ------
// block = dst node; 8 warps = 8 heads; lane = dim within head.
__global__ __launch_bounds__(256)
void attn_kernel(const float* __restrict__ spde,
                 const float* __restrict__ etb) {
    int d = blockIdx.x;
    int t = threadIdx.x, h = t >> 5;
    int beg = g_off[d], end = g_off[d + 1];
    float q  = g_Q[d*CC + t];
    float et = etb[0];
    float sum = 0.0f, acc = 0.0f;
    for (int i = beg; i < end; i++) {
        int pk = g_elist[i];
        int e = pk & 0x1FFFF;
        int s = pk >> 17;
        float kv = g_K[s*CC + t];
        float p = q * kv;
        #pragma unroll
        for (int o = 16; o; o >>= 1) p += __shfl_xor_sync(0xffffffffu, p, o);
        int sp = G_SPD[e];
        if (sp == 0)   // probe k=3 inline against F3; else unreachable -> 4
            sp = ((g_F3[s*FW + (d >> 5)] >> (d & 31)) & 1u) ? 3 : 4;
        float ex = expf(p * 0.17677669529663687f + spde[sp*HH + h] + et);
        sum += ex;
        acc += ex * g_V[s*CC + t];
    }
    float inv = (sum > 0.0f) ? (1.0f / sum) : 0.0f;
    g_msg[d*CC + t] = acc * inv;
}

// ---------------- launch ----------------------------------------------------
extern "C" void kernel_launch(void* const* d_in, const int* in_sizes, int n_in,
                              void* d_out, int out_size) {
    const float* x      = (const float*)d_in[0];
    const int*   ei     = (const int*)  d_in[1];
    const float* Wq     = (const float*)d_in[2];
    const float* bq     = (const float*)d_in[3];
    const float* Wk     = (const float*)d_in[4];
    const float* bk     = (const float*)d_in[5];
    const float* Wv     = (const float*)d_in[6];
    const float* bv     = (const float*)d_in[7];
    const float* Wo     = (const float*)d_in[8];
    const float* bo     = (const float*)d_in[9];
    const float* W1     = (const float*)d_in[10];
    const float* b1     = (const float*)d_in[11];
    const float* W2     = (const float*)d_in[12];
    const float* b2     = (const float*)d_in[13];
    const float* g1     = (const float*)d_in[14];
    const float* beta1  = (const float*)d_in[15];
    const float* g2     = (const float*)d_in[16];
    const float* beta2  = (const float*)d_in[17];
    const float* spde   = (const float*)d_in[18];
    const float* ide    = (const float*)d_in[19];
    const float* ode    = (const float*)d_in[20];
    const float* etb    = (const float*)d_in[21];
    float* out = (float*)d_out;

    void* p_zblk;
    unsigned *pF2, *pF3;
    float *pQ, *pK, *pV, *p_xn, *p_xin, *p_msgf, *p_h, *p_hn, *p_ff1;
    cudaGetSymbolAddress(&p_zblk, g_zblk);
    cudaGetSymbolAddress((void**)&pF2,   g_F2);
    cudaGetSymbolAddress((void**)&pF3,   g_F3);
    cudaGetSymbolAddress((void**)&pQ,    g_Q);
    cudaGetSymbolAddress((void**)&pK,    g_K);
    cudaGetSymbolAddress((void**)&pV,    g_V);
    cudaGetSymbolAddress((void**)&p_xin, g_xin);
    cudaGetSymbolAddress((void**)&p_xn,  g_xn);
    cudaGetSymbolAddress((void**)&p_msgf,g_msg);
    cudaGetSymbolAddress((void**)&p_h,   g_h);
    cudaGetSymbolAddress((void**)&p_hn,  g_hn);
    cudaGetSymbolAddress((void**)&p_ff1, g_ff1);

    unsigned* F1 = (unsigned*)p_zblk + OFF_F1;

    // ONE reset (indeg, outdeg, spd, F1); F2/F3 fully overwritten by gather
    cudaMemsetAsync(p_zblk, 0, (size_t)ZTOT * sizeof(unsigned));

    // degrees + SPD step-1 in one edge pass; CSR build
    deg_prop1_kernel<<<EE/256, 256>>>(ei);
    scan_kernel<<<1, 1024>>>();
    fill_kernel<<<EE/256, 256>>>(ei);

    // SPD: CSR gather propagation, probe fused; k=3 probed inside attn
    prop_gather_kernel<<<NN, 128>>>(F1, pF2, 1);
    prop_gather_kernel<<<NN, 128>>>(pF2, pF3, 2);

    // fused xin + LN1, then fused QKV projection
    xin_ln_kernel<<<NN, CC>>>(x, ide, ode, g1, beta1);
    dim3 blk(256);
    dim3 grdQKV(CC/GTN, NN/GTM, 3);  // 4 x 64 x 3
    gemm_qkv<<<grdQKV, blk>>>(p_xn, Wq, bq, Wk, bk, Wv, bv, pQ, pK, pV);

    // fused edge attention (CSR gather, no atomics, probe3 inline)
    attn_kernel<<<NN, 256>>>(spde, etb);

    // h = x_in + msg @ Wo + bo
    dim3 grdC(CC/GTN, NN/GTM);       // 4 x 64
    gemm_tf32<<<grdC, blk>>>(p_msgf, Wo, bo, p_xin, p_h, CC, CC, 1);

    // LN2 + FFN
    ln_kernel<<<NN, CC>>>(p_h, g2, beta2, p_hn);
    dim3 grdF1(C4/GTN, NN/GTM);      // 16 x 64
    gemm_tf32<<<grdF1, blk>>>(p_hn, W1, b1, nullptr, p_ff1, CC, C4, 2);
    gemm_tf32<<<grdC,  blk>>>(p_ff1, W2, b2, p_h, out, C4, CC, 1);
}

// round 9
// speedup vs baseline: 2.5520x; 1.0248x over previous
#include <cuda_runtime.h>
#include <cuda_bf16.h>

#define NN 4096
#define CC 256
#define HH 8
#define DHH 32
#define EE 32768
#define FW 128            // 4096 bits / 32 words per bitset row
#define C4 (4*CC)         // 1024

// ---------------- zeroed scratch: ONE block, ONE memset ---------------------
#define OFF_INDEG  0
#define OFF_OUTDEG (OFF_INDEG  + NN)
#define OFF_SPD    (OFF_OUTDEG + NN)
#define OFF_F1     (OFF_SPD    + EE)
#define ZTOT       (OFF_F1     + NN*FW)
__device__ unsigned g_zblk[ZTOT];

#define G_INDEG  ((int*)(g_zblk + OFF_INDEG))
#define G_OUTDEG ((int*)(g_zblk + OFF_OUTDEG))
#define G_SPD    ((int*)(g_zblk + OFF_SPD))
#define G_F1     (g_zblk + OFF_F1)

// ---------------- other scratch (fully overwritten, no zeroing) -------------
__device__ unsigned g_F2[NN*FW];
__device__ unsigned g_F3[NN*FW];
__device__ int      g_off[NN + 1];
__device__ int      g_cur[NN];
__device__ int      g_elist[EE];     // packed (src<<17)|e, ordered by dst
__device__ float    g_xin[NN*CC];
__device__ float    g_xn [NN*CC];
__device__ float    g_Q  [NN*CC];
__device__ float    g_K  [NN*CC];
__device__ float    g_V  [NN*CC];
__device__ float    g_msg[NN*CC];
__device__ float    g_h  [NN*CC];
__device__ float    g_hn [NN*CC];
__device__ float    g_ff1[NN*C4];

// ---------------- degrees + SPD step-1 (merged edge pass) -------------------
__global__ void deg_prop1_kernel(const int* __restrict__ ei) {
    int e = blockIdx.x * blockDim.x + threadIdx.x;
    if (e < EE) {
        int s = ei[e], d = ei[EE + e];
        atomicAdd(&G_OUTDEG[s], 1);
        atomicAdd(&G_INDEG [d], 1);
        atomicOr(&G_F1[d*FW + (s >> 5)], 1u << (s & 31));
    }
}

// ---------------- CSR build: exclusive scan of indeg (1 block, 1024 thr) ---
__global__ __launch_bounds__(1024) void scan_kernel() {
    __shared__ int wsum[32];
    int t = threadIdx.x;
    int v0 = G_INDEG[4*t+0], v1 = G_INDEG[4*t+1];
    int v2 = G_INDEG[4*t+2], v3 = G_INDEG[4*t+3];
    int s = v0 + v1 + v2 + v3;
    int lane = t & 31, w = t >> 5;
    int x = s;
    #pragma unroll
    for (int o = 1; o < 32; o <<= 1) {
        int y = __shfl_up_sync(0xffffffffu, x, o);
        if (lane >= o) x += y;
    }
    if (lane == 31) wsum[w] = x;
    __syncthreads();
    if (w == 0) {
        int y = wsum[lane];
        #pragma unroll
        for (int o = 1; o < 32; o <<= 1) {
            int z = __shfl_up_sync(0xffffffffu, y, o);
            if (lane >= o) y += z;
        }
        wsum[lane] = y;
    }
    __syncthreads();
    int base = (w > 0 ? wsum[w-1] : 0) + (x - s);  // exclusive prefix
    int o0 = base, o1 = o0 + v0, o2 = o1 + v1, o3 = o2 + v2;
    g_off[4*t+0] = o0; g_cur[4*t+0] = o0;
    g_off[4*t+1] = o1; g_cur[4*t+1] = o1;
    g_off[4*t+2] = o2; g_cur[4*t+2] = o2;
    g_off[4*t+3] = o3; g_cur[4*t+3] = o3;
    if (t == 1023) g_off[NN] = o3 + v3;
}

__global__ void fill_kernel(const int* __restrict__ ei) {
    int e = blockIdx.x * blockDim.x + threadIdx.x;
    if (e < EE) {
        int s = ei[e], d = ei[EE + e];
        int pos = atomicAdd(&g_cur[d], 1);
        g_elist[pos] = (s << 17) | e;
    }
}

// ---------------- SPD: CSR gather propagation + inline probe ---------------
// 4 dsts per block; 32 lanes per dst, lane owns 4 words (uint4).
// Fn fully written -> no pre-zeroing. Probe step k inline.
__global__ __launch_bounds__(128)
void prop_gather_kernel(const unsigned* __restrict__ F,
                        unsigned* __restrict__ Fn, int k) {
    int grp = threadIdx.x >> 5, l = threadIdx.x & 31;
    int d = blockIdx.x * 4 + grp;
    int beg = g_off[d], end = g_off[d + 1];
    uint4 acc = make_uint4(0u, 0u, 0u, 0u);
    for (int i = beg; i < end; i++) {
        int s = g_elist[i] >> 17;
        uint4 v = *(const uint4*)&F[s*FW + l*4];
        acc.x |= v.x; acc.y |= v.y; acc.z |= v.z; acc.w |= v.w;
    }
    *(uint4*)&Fn[d*FW + l*4] = acc;
    // probe step k for this dst's in-edges
    for (int i = beg + l; i < end; i += 32) {
        int pk = g_elist[i];
        int e = pk & 0x1FFFF, s = pk >> 17;
        if (G_SPD[e] == 0 && ((F[s*FW + (d >> 5)] >> (d & 31)) & 1u))
            G_SPD[e] = k;
    }
}

// ---------------- fused xin + LayerNorm1 (block per row, 256 threads) -------
__global__ void xin_ln_kernel(const float* __restrict__ x,
                              const float* __restrict__ ide,
                              const float* __restrict__ ode,
                              const float* __restrict__ g,
                              const float* __restrict__ b) {
    __shared__ float sh[16];
    int n = blockIdx.x, t = threadIdx.x;
    int bi = min(31 - __clz(G_INDEG [n] + 1), 8);
    int bo = min(31 - __clz(G_OUTDEG[n] + 1), 8);
    float v = x[n*CC + t] + ide[bi*CC + t] + ode[bo*CC + t];
    g_xin[n*CC + t] = v;
    float s = v;
    #pragma unroll
    for (int o = 16; o; o >>= 1) s += __shfl_xor_sync(0xffffffffu, s, o);
    if ((t & 31) == 0) sh[t >> 5] = s;
    __syncthreads();
    if (t == 0) { float a = 0; for (int i = 0; i < 8; i++) a += sh[i]; sh[8] = a * (1.0f/CC); }
    __syncthreads();
    float mu = sh[8];
    float d  = v - mu;
    float q  = d * d;
    #pragma unroll
    for (int o = 16; o; o >>= 1) q += __shfl_xor_sync(0xffffffffu, q, o);
    if ((t & 31) == 0) sh[t >> 5] = q;
    __syncthreads();
    if (t == 0) { float a = 0; for (int i = 0; i < 8; i++) a += sh[i]; sh[9] = rsqrtf(a * (1.0f/CC) + 1e-5f); }
    __syncthreads();
    g_xn[n*CC + t] = g[t] * d * sh[9] + b[t];
}

// ---------------- plain LayerNorm (block per row, 256 threads) --------------
__global__ void ln_kernel(const float* __restrict__ in,
                          const float* __restrict__ g,
                          const float* __restrict__ b,
                          float* __restrict__ out) {
    __shared__ float sh[16];
    int n = blockIdx.x, t = threadIdx.x;
    float v = in[n*CC + t];
    float s = v;
    #pragma unroll
    for (int o = 16; o; o >>= 1) s += __shfl_xor_sync(0xffffffffu, s, o);
    if ((t & 31) == 0) sh[t >> 5] = s;
    __syncthreads();
    if (t == 0) { float a = 0; for (int i = 0; i < 8; i++) a += sh[i]; sh[8] = a * (1.0f/CC); }
    __syncthreads();
    float mu = sh[8];
    float d  = v - mu;
    float q  = d * d;
    #pragma unroll
    for (int o = 16; o; o >>= 1) q += __shfl_xor_sync(0xffffffffu, q, o);
    if ((t & 31) == 0) sh[t >> 5] = q;
    __syncthreads();
    if (t == 0) { float a = 0; for (int i = 0; i < 8; i++) a += sh[i]; sh[9] = rsqrtf(a * (1.0f/CC) + 1e-5f); }
    __syncthreads();
    out[n*CC + t] = g[t] * d * sh[9] + b[t];
}

// ---------------- tf32 tensor-core GEMM, 3-stage cp.async -------------------
__device__ __forceinline__ unsigned to_tf32_u(float x) {
    unsigned u;
    asm("cvt.rna.tf32.f32 %0, %1;" : "=r"(u) : "f"(x));
    return u;
}

#define GTM 64
#define GTN 64
#define GTK 32
#define A_ST (GTM*(GTK+4))          // 2304 floats per A stage
#define B_ST (GTK*(GTN+4))          // 2176 floats per B stage
#define GSMEM ((3*(A_ST+B_ST))*4)   // 53760 bytes

// block tile 64x64x32, 3-stage cp.async, 8 warps = 2(M) x 4(N),
// warp tile 32x16 = 2x2 mma.m16n8k8 tiles.
__device__ __forceinline__
void gemm_core(const float* __restrict__ A, const float* __restrict__ B,
               const float* __restrict__ bias, const float* __restrict__ resid,
               float* __restrict__ C, int K, int N, int mode,
               int m0, int n0) {
    extern __shared__ float smem[];
    float* As = smem;                 // [3][64][36]
    float* Bs = smem + 3*A_ST;        // [3][32][68]
    #define AS(s,r,k) As[(s)*A_ST + (r)*(GTK+4) + (k)]
    #define BS(s,r,n) Bs[(s)*B_ST + (r)*(GTN+4) + (n)]
    int tid  = threadIdx.x;
    int wid  = tid >> 5, lane = tid & 31;
    int warpM = wid & 1, warpN = wid >> 1;
    int lm = lane >> 2, lk = lane & 3;

    float c[2][2][4];
    #pragma unroll
    for (int i = 0; i < 2; i++)
        #pragma unroll
        for (int j = 0; j < 2; j++)
            #pragma unroll
            for (int q = 0; q < 4; q++) c[i][j][q] = 0.0f;

    int ar = tid >> 3;            // 0..31 (2 rounds cover 64 rows)
    int ak = (tid & 7) * 4;       // 0..28
    int bk = tid >> 4;            // 0..15 (2 rounds cover 32 k-rows)
    int bn = (tid & 15) * 4;      // 0..60

    auto prefetch = [&](int buf, int k0) {
        #pragma unroll
        for (int p = 0; p < 2; p++) {
            int row = ar + p * 32;
            unsigned dst = (unsigned)__cvta_generic_to_shared(&AS(buf, row, ak));
            asm volatile("cp.async.cg.shared.global [%0], [%1], 16;"
                         :: "r"(dst), "l"(&A[(size_t)(m0 + row) * K + k0 + ak]));
        }
        #pragma unroll
        for (int p = 0; p < 2; p++) {
            int kr = bk + p * 16;
            unsigned dst = (unsigned)__cvta_generic_to_shared(&BS(buf, kr, bn));
            asm volatile("cp.async.cg.shared.global [%0], [%1], 16;"
                         :: "r"(dst), "l"(&B[(size_t)(k0 + kr) * N + n0 + bn]));
        }
        asm volatile("cp.async.commit_group;");
    };

    int nt = K / GTK;            // >= 8
    prefetch(0, 0);
    prefetch(1, GTK);
    for (int t = 0; t < nt; t++) {
        if (t + 2 < nt) {
            prefetch((t + 2) % 3, (t + 2) * GTK);
            asm volatile("cp.async.wait_group 2;");
        } else if (t + 1 < nt) {
            asm volatile("cp.async.wait_group 1;");
        } else {
            asm volatile("cp.async.wait_group 0;");
        }
        __syncthreads();
        int buf = t % 3;
        #pragma unroll
        for (int k8 = 0; k8 < GTK; k8 += 8) {
            unsigned a[2][4], b[2][2];
            #pragma unroll
            for (int i = 0; i < 2; i++) {
                int r = warpM * 32 + i * 16 + lm;
                a[i][0] = to_tf32_u(AS(buf, r    , k8 + lk    ));
                a[i][1] = to_tf32_u(AS(buf, r + 8, k8 + lk    ));
                a[i][2] = to_tf32_u(AS(buf, r    , k8 + lk + 4));
                a[i][3] = to_tf32_u(AS(buf, r + 8, k8 + lk + 4));
            }
            #pragma unroll
            for (int j = 0; j < 2; j++) {
                int cn = warpN * 16 + j * 8 + lm;
                b[j][0] = to_tf32_u(BS(buf, k8 + lk    , cn));
                b[j][1] = to_tf32_u(BS(buf, k8 + lk + 4, cn));
            }
            #pragma unroll
            for (int i = 0; i < 2; i++)
                #pragma unroll
                for (int j = 0; j < 2; j++) {
                    asm volatile(
                        "mma.sync.aligned.m16n8k8.row.col.f32.tf32.tf32.f32 "
                        "{%0,%1,%2,%3}, {%4,%5,%6,%7}, {%8,%9}, {%0,%1,%2,%3};"
                        : "+f"(c[i][j][0]), "+f"(c[i][j][1]),
                          "+f"(c[i][j][2]), "+f"(c[i][j][3])
                        : "r"(a[i][0]), "r"(a[i][1]), "r"(a[i][2]), "r"(a[i][3]),
                          "r"(b[j][0]), "r"(b[j][1]));
                }
        }
        __syncthreads();
    }

    #pragma unroll
    for (int i = 0; i < 2; i++) {
        #pragma unroll
        for (int j = 0; j < 2; j++) {
            int r  = m0 + warpM * 32 + i * 16 + lm;
            int cn = n0 + warpN * 16 + j * 8 + 2 * lk;
            float b0 = bias[cn], b1 = bias[cn + 1];
            #pragma unroll
            for (int half = 0; half < 2; half++) {
                int rr = r + half * 8;
                float v0 = c[i][j][half * 2 + 0] + b0;
                float v1 = c[i][j][half * 2 + 1] + b1;
                if (mode == 1) {
                    v0 += resid[(size_t)rr * N + cn];
                    v1 += resid[(size_t)rr * N + cn + 1];
                } else if (mode == 2) {
                    v0 = 0.5f * v0 * (1.0f + erff(v0 * 0.70710678118654752f));
                    v1 = 0.5f * v1 * (1.0f + erff(v1 * 0.70710678118654752f));
                }
                *(float2*)&C[(size_t)rr * N + cn] = make_float2(v0, v1);
            }
        }
    }
    #undef AS
    #undef BS
}

__global__ __launch_bounds__(256)
void gemm_tf32(const float* __restrict__ A, const float* __restrict__ B,
               const float* __restrict__ bias, const float* __restrict__ resid,
               float* __restrict__ C, int K, int N, int mode) {
    gemm_core(A, B, bias, resid, C, K, N, mode,
              blockIdx.y * GTM, blockIdx.x * GTN);
}

// fused QKV: blockIdx.z selects weight/bias/output
__global__ __launch_bounds__(256)
void gemm_qkv(const float* __restrict__ A,
              const float* __restrict__ Wq, const float* __restrict__ bq,
              const float* __restrict__ Wk, const float* __restrict__ bk,
              const float* __restrict__ Wv, const float* __restrict__ bv,
              float* __restrict__ Q, float* __restrict__ K,
              float* __restrict__ V) {
    int z = blockIdx.z;
    const float* B    = (z == 0) ? Wq : (z == 1) ? Wk : Wv;
    const float* bias = (z == 0) ? bq : (z == 1) ? bk : bv;
    float*       C    = (z == 0) ? Q  : (z == 1) ? K  : V;
    gemm_core(A, B, bias, nullptr, C, CC, CC, 0,
              blockIdx.y * GTM, blockIdx.x * GTN);
}

// ---------------- fused single-pass edge attention (+probe k=3 inline) ------
// block = dst node; 8 warps = 8 heads; lane = dim within head.
__global__ __launch_bounds__(256)
void attn_kernel(const float* __restrict__ spde,
                 const float* __restrict__ etb) {
    int d = blockIdx.x;
    int t = threadIdx.x, h = t >> 5;
    int beg = g_off[d], end = g_off[d + 1];
    float q  = g_Q[d*CC + t];
    float et = etb[0];
    float sum = 0.0f, acc = 0.0f;
    for (int i = beg; i < end; i++) {
        int pk = g_elist[i];
        int e = pk & 0x1FFFF;
        int s = pk >> 17;
        float kv = g_K[s*CC + t];
        float p = q * kv;
        #pragma unroll
        for (int o = 16; o; o >>= 1) p += __shfl_xor_sync(0xffffffffu, p, o);
        int sp = G_SPD[e];
        if (sp == 0)   // probe k=3 inline against F3; else unreachable -> 4
            sp = ((g_F3[s*FW + (d >> 5)] >> (d & 31)) & 1u) ? 3 : 4;
        float ex = expf(p * 0.17677669529663687f + spde[sp*HH + h] + et);
        sum += ex;
        acc += ex * g_V[s*CC + t];
    }
    float inv = (sum > 0.0f) ? (1.0f / sum) : 0.0f;
    g_msg[d*CC + t] = acc * inv;
}

// ---------------- launch ----------------------------------------------------
extern "C" void kernel_launch(void* const* d_in, const int* in_sizes, int n_in,
                              void* d_out, int out_size) {
    const float* x      = (const float*)d_in[0];
    const int*   ei     = (const int*)  d_in[1];
    const float* Wq     = (const float*)d_in[2];
    const float* bq     = (const float*)d_in[3];
    const float* Wk     = (const float*)d_in[4];
    const float* bk     = (const float*)d_in[5];
    const float* Wv     = (const float*)d_in[6];
    const float* bv     = (const float*)d_in[7];
    const float* Wo     = (const float*)d_in[8];
    const float* bo     = (const float*)d_in[9];
    const float* W1     = (const float*)d_in[10];
    const float* b1     = (const float*)d_in[11];
    const float* W2     = (const float*)d_in[12];
    const float* b2     = (const float*)d_in[13];
    const float* g1     = (const float*)d_in[14];
    const float* beta1  = (const float*)d_in[15];
    const float* g2     = (const float*)d_in[16];
    const float* beta2  = (const float*)d_in[17];
    const float* spde   = (const float*)d_in[18];
    const float* ide    = (const float*)d_in[19];
    const float* ode    = (const float*)d_in[20];
    const float* etb    = (const float*)d_in[21];
    float* out = (float*)d_out;

    void* p_zblk;
    unsigned *pF2, *pF3;
    float *pQ, *pK, *pV, *p_xn, *p_xin, *p_msgf, *p_h, *p_hn, *p_ff1;
    cudaGetSymbolAddress(&p_zblk, g_zblk);
    cudaGetSymbolAddress((void**)&pF2,   g_F2);
    cudaGetSymbolAddress((void**)&pF3,   g_F3);
    cudaGetSymbolAddress((void**)&pQ,    g_Q);
    cudaGetSymbolAddress((void**)&pK,    g_K);
    cudaGetSymbolAddress((void**)&pV,    g_V);
    cudaGetSymbolAddress((void**)&p_xin, g_xin);
    cudaGetSymbolAddress((void**)&p_xn,  g_xn);
    cudaGetSymbolAddress((void**)&p_msgf,g_msg);
    cudaGetSymbolAddress((void**)&p_h,   g_h);
    cudaGetSymbolAddress((void**)&p_hn,  g_hn);
    cudaGetSymbolAddress((void**)&p_ff1, g_ff1);

    unsigned* F1 = (unsigned*)p_zblk + OFF_F1;

    // allow > 48KB dynamic smem for the 3-stage GEMM
    static int smem_set = 0;
    if (!smem_set) {
        cudaFuncSetAttribute(gemm_tf32, cudaFuncAttributeMaxDynamicSharedMemorySize, GSMEM);
        cudaFuncSetAttribute(gemm_qkv,  cudaFuncAttributeMaxDynamicSharedMemorySize, GSMEM);
        smem_set = 1;
    }

    // ONE reset (indeg, outdeg, spd, F1); F2/F3 fully overwritten by gather
    cudaMemsetAsync(p_zblk, 0, (size_t)ZTOT * sizeof(unsigned));

    // degrees + SPD step-1 in one edge pass; CSR build
    deg_prop1_kernel<<<EE/256, 256>>>(ei);
    scan_kernel<<<1, 1024>>>();
    fill_kernel<<<EE/256, 256>>>(ei);

    // SPD: CSR gather propagation (uint4), probe fused; k=3 probed inside attn
    prop_gather_kernel<<<NN/4, 128>>>(F1, pF2, 1);
    prop_gather_kernel<<<NN/4, 128>>>(pF2, pF3, 2);

    // fused xin + LN1, then fused QKV projection
    xin_ln_kernel<<<NN, CC>>>(x, ide, ode, g1, beta1);
    dim3 blk(256);
    dim3 grdQKV(CC/GTN, NN/GTM, 3);  // 4 x 64 x 3
    gemm_qkv<<<grdQKV, blk, GSMEM>>>(p_xn, Wq, bq, Wk, bk, Wv, bv, pQ, pK, pV);

    // fused edge attention (CSR gather, no atomics, probe3 inline)
    attn_kernel<<<NN, 256>>>(spde, etb);

    // h = x_in + msg @ Wo + bo
    dim3 grdC(CC/GTN, NN/GTM);       // 4 x 64
    gemm_tf32<<<grdC, blk, GSMEM>>>(p_msgf, Wo, bo, p_xin, p_h, CC, CC, 1);

    // LN2 + FFN
    ln_kernel<<<NN, CC>>>(p_h, g2, beta2, p_hn);
    dim3 grdF1(C4/GTN, NN/GTM);      // 16 x 64
    gemm_tf32<<<grdF1, blk, GSMEM>>>(p_hn, W1, b1, nullptr, p_ff1, CC, C4, 2);
    gemm_tf32<<<grdC,  blk, GSMEM>>>(p_ff1, W2, b2, p_h, out, C4, CC, 1);
}

// round 10
// speedup vs baseline: 2.7157x; 1.0642x over previous
#include <cuda_runtime.h>
#include <cuda_bf16.h>

#define NN 4096
#define CC 256
#define HH 8
#define DHH 32
#define EE 32768
#define FW 128            // 4096 bits / 32 words per bitset row
#define C4 (4*CC)         // 1024

// ---------------- zeroed scratch: ONE block, ONE memset ---------------------
#define OFF_INDEG  0
#define OFF_OUTDEG (OFF_INDEG  + NN)
#define OFF_SPD    (OFF_OUTDEG + NN)
#define OFF_F1     (OFF_SPD    + EE)
#define ZTOT       (OFF_F1     + NN*FW)
__device__ unsigned g_zblk[ZTOT];

#define G_INDEG  ((int*)(g_zblk + OFF_INDEG))
#define G_OUTDEG ((int*)(g_zblk + OFF_OUTDEG))
#define G_SPD    ((int*)(g_zblk + OFF_SPD))
#define G_F1     (g_zblk + OFF_F1)

// ---------------- other scratch (fully overwritten, no zeroing) -------------
__device__ unsigned g_F2[NN*FW];
__device__ unsigned g_F3[NN*FW];
__device__ int      g_off[NN + 1];
__device__ int      g_cur[NN];
__device__ int      g_elist[EE];     // packed (src<<17)|e, ordered by dst
__device__ float    g_xin[NN*CC];
__device__ float    g_xn [NN*CC];
__device__ float    g_Q  [NN*CC];
__device__ float    g_K  [NN*CC];
__device__ float    g_V  [NN*CC];
__device__ float    g_msg[NN*CC];
__device__ float    g_h  [NN*CC];
__device__ float    g_hn [NN*CC];
__device__ float    g_ff1[NN*C4];

// ---------------- degrees + SPD step-1 (merged edge pass) -------------------
__global__ void deg_prop1_kernel(const int* __restrict__ ei) {
    int e = blockIdx.x * blockDim.x + threadIdx.x;
    if (e < EE) {
        int s = ei[e], d = ei[EE + e];
        atomicAdd(&G_OUTDEG[s], 1);
        atomicAdd(&G_INDEG [d], 1);
        atomicOr(&G_F1[d*FW + (s >> 5)], 1u << (s & 31));
    }
}

// ---------------- CSR build: exclusive scan of indeg (1 block, 1024 thr) ---
__global__ __launch_bounds__(1024) void scan_kernel() {
    __shared__ int wsum[32];
    int t = threadIdx.x;
    int v0 = G_INDEG[4*t+0], v1 = G_INDEG[4*t+1];
    int v2 = G_INDEG[4*t+2], v3 = G_INDEG[4*t+3];
    int s = v0 + v1 + v2 + v3;
    int lane = t & 31, w = t >> 5;
    int x = s;
    #pragma unroll
    for (int o = 1; o < 32; o <<= 1) {
        int y = __shfl_up_sync(0xffffffffu, x, o);
        if (lane >= o) x += y;
    }
    if (lane == 31) wsum[w] = x;
    __syncthreads();
    if (w == 0) {
        int y = wsum[lane];
        #pragma unroll
        for (int o = 1; o < 32; o <<= 1) {
            int z = __shfl_up_sync(0xffffffffu, y, o);
            if (lane >= o) y += z;
        }
        wsum[lane] = y;
    }
    __syncthreads();
    int base = (w > 0 ? wsum[w-1] : 0) + (x - s);  // exclusive prefix
    int o0 = base, o1 = o0 + v0, o2 = o1 + v1, o3 = o2 + v2;
    g_off[4*t+0] = o0; g_cur[4*t+0] = o0;
    g_off[4*t+1] = o1; g_cur[4*t+1] = o1;
    g_off[4*t+2] = o2; g_cur[4*t+2] = o2;
    g_off[4*t+3] = o3; g_cur[4*t+3] = o3;
    if (t == 1023) g_off[NN] = o3 + v3;
}

__global__ void fill_kernel(const int* __restrict__ ei) {
    int e = blockIdx.x * blockDim.x + threadIdx.x;
    if (e < EE) {
        int s = ei[e], d = ei[EE + e];
        int pos = atomicAdd(&g_cur[d], 1);
        g_elist[pos] = (s << 17) | e;
    }
}

// ---------------- SPD: CSR gather propagation + inline probe ---------------
// 4 dsts per block; 32 lanes per dst, lane owns 4 words (uint4).
__global__ __launch_bounds__(128)
void prop_gather_kernel(const unsigned* __restrict__ F,
                        unsigned* __restrict__ Fn, int k) {
    int grp = threadIdx.x >> 5, l = threadIdx.x & 31;
    int d = blockIdx.x * 4 + grp;
    int beg = g_off[d], end = g_off[d + 1];
    uint4 acc = make_uint4(0u, 0u, 0u, 0u);
    for (int i = beg; i < end; i++) {
        int s = g_elist[i] >> 17;
        uint4 v = *(const uint4*)&F[s*FW + l*4];
        acc.x |= v.x; acc.y |= v.y; acc.z |= v.z; acc.w |= v.w;
    }
    *(uint4*)&Fn[d*FW + l*4] = acc;
    for (int i = beg + l; i < end; i += 32) {
        int pk = g_elist[i];
        int e = pk & 0x1FFFF, s = pk >> 17;
        if (G_SPD[e] == 0 && ((F[s*FW + (d >> 5)] >> (d & 31)) & 1u))
            G_SPD[e] = k;
    }
}

// ---------------- fused xin + LayerNorm1 (block per row, 256 threads) -------
__global__ void xin_ln_kernel(const float* __restrict__ x,
                              const float* __restrict__ ide,
                              const float* __restrict__ ode,
                              const float* __restrict__ g,
                              const float* __restrict__ b) {
    __shared__ float sh[16];
    int n = blockIdx.x, t = threadIdx.x;
    int bi = min(31 - __clz(G_INDEG [n] + 1), 8);
    int bo = min(31 - __clz(G_OUTDEG[n] + 1), 8);
    float v = x[n*CC + t] + ide[bi*CC + t] + ode[bo*CC + t];
    g_xin[n*CC + t] = v;
    float s = v;
    #pragma unroll
    for (int o = 16; o; o >>= 1) s += __shfl_xor_sync(0xffffffffu, s, o);
    if ((t & 31) == 0) sh[t >> 5] = s;
    __syncthreads();
    if (t == 0) { float a = 0; for (int i = 0; i < 8; i++) a += sh[i]; sh[8] = a * (1.0f/CC); }
    __syncthreads();
    float mu = sh[8];
    float d  = v - mu;
    float q  = d * d;
    #pragma unroll
    for (int o = 16; o; o >>= 1) q += __shfl_xor_sync(0xffffffffu, q, o);
    if ((t & 31) == 0) sh[t >> 5] = q;
    __syncthreads();
    if (t == 0) { float a = 0; for (int i = 0; i < 8; i++) a += sh[i]; sh[9] = rsqrtf(a * (1.0f/CC) + 1e-5f); }
    __syncthreads();
    g_xn[n*CC + t] = g[t] * d * sh[9] + b[t];
}

// ---------------- plain LayerNorm (block per row, 256 threads) --------------
__global__ void ln_kernel(const float* __restrict__ in,
                          const float* __restrict__ g,
                          const float* __restrict__ b,
                          float* __restrict__ out) {
    __shared__ float sh[16];
    int n = blockIdx.x, t = threadIdx.x;
    float v = in[n*CC + t];
    float s = v;
    #pragma unroll
    for (int o = 16; o; o >>= 1) s += __shfl_xor_sync(0xffffffffu, s, o);
    if ((t & 31) == 0) sh[t >> 5] = s;
    __syncthreads();
    if (t == 0) { float a = 0; for (int i = 0; i < 8; i++) a += sh[i]; sh[8] = a * (1.0f/CC); }
    __syncthreads();
    float mu = sh[8];
    float d  = v - mu;
    float q  = d * d;
    #pragma unroll
    for (int o = 16; o; o >>= 1) q += __shfl_xor_sync(0xffffffffu, q, o);
    if ((t & 31) == 0) sh[t >> 5] = q;
    __syncthreads();
    if (t == 0) { float a = 0; for (int i = 0; i < 8; i++) a += sh[i]; sh[9] = rsqrtf(a * (1.0f/CC) + 1e-5f); }
    __syncthreads();
    out[n*CC + t] = g[t] * d * sh[9] + b[t];
}

// ---------------- tf32 tensor-core GEMM, 3-stage cp.async -------------------
__device__ __forceinline__ unsigned to_tf32_u(float x) {
    unsigned u;
    asm("cvt.rna.tf32.f32 %0, %1;" : "=r"(u) : "f"(x));
    return u;
}

#define GTM 64
#define GTN 64
#define GTK 32
#define A_ST (GTM*(GTK+4))          // 2304 floats per A stage
#define B_ST (GTK*(GTN+4))          // 2176 floats per B stage
#define GSMEM ((3*(A_ST+B_ST))*4)   // 53760 bytes

__device__ __forceinline__
void gemm_core(const float* __restrict__ A, const float* __restrict__ B,
               const float* __restrict__ bias, const float* __restrict__ resid,
               float* __restrict__ C, int K, int N, int mode,
               int m0, int n0) {
    extern __shared__ float smem[];
    float* As = smem;                 // [3][64][36]
    float* Bs = smem + 3*A_ST;        // [3][32][68]
    #define AS(s,r,k) As[(s)*A_ST + (r)*(GTK+4) + (k)]
    #define BS(s,r,n) Bs[(s)*B_ST + (r)*(GTN+4) + (n)]
    int tid  = threadIdx.x;
    int wid  = tid >> 5, lane = tid & 31;
    int warpM = wid & 1, warpN = wid >> 1;
    int lm = lane >> 2, lk = lane & 3;

    float c[2][2][4];
    #pragma unroll
    for (int i = 0; i < 2; i++)
        #pragma unroll
        for (int j = 0; j < 2; j++)
            #pragma unroll
            for (int q = 0; q < 4; q++) c[i][j][q] = 0.0f;

    int ar = tid >> 3;            // 0..31 (2 rounds cover 64 rows)
    int ak = (tid & 7) * 4;       // 0..28
    int bk = tid >> 4;            // 0..15 (2 rounds cover 32 k-rows)
    int bn = (tid & 15) * 4;      // 0..60

    auto prefetch = [&](int buf, int k0) {
        #pragma unroll
        for (int p = 0; p < 2; p++) {
            int row = ar + p * 32;
            unsigned dst = (unsigned)__cvta_generic_to_shared(&AS(buf, row, ak));
            asm volatile("cp.async.cg.shared.global [%0], [%1], 16;"
                         :: "r"(dst), "l"(&A[(size_t)(m0 + row) * K + k0 + ak]));
        }
        #pragma unroll
        for (int p = 0; p < 2; p++) {
            int kr = bk + p * 16;
            unsigned dst = (unsigned)__cvta_generic_to_shared(&BS(buf, kr, bn));
            asm volatile("cp.async.cg.shared.global [%0], [%1], 16;"
                         :: "r"(dst), "l"(&B[(size_t)(k0 + kr) * N + n0 + bn]));
        }
        asm volatile("cp.async.commit_group;");
    };

    int nt = K / GTK;            // >= 8
    prefetch(0, 0);
    prefetch(1, GTK);
    for (int t = 0; t < nt; t++) {
        if (t + 2 < nt) {
            prefetch((t + 2) % 3, (t + 2) * GTK);
            asm volatile("cp.async.wait_group 2;");
        } else if (t + 1 < nt) {
            asm volatile("cp.async.wait_group 1;");
        } else {
            asm volatile("cp.async.wait_group 0;");
        }
        __syncthreads();
        int buf = t % 3;
        #pragma unroll
        for (int k8 = 0; k8 < GTK; k8 += 8) {
            unsigned a[2][4], b[2][2];
            #pragma unroll
            for (int i = 0; i < 2; i++) {
                int r = warpM * 32 + i * 16 + lm;
                a[i][0] = to_tf32_u(AS(buf, r    , k8 + lk    ));
                a[i][1] = to_tf32_u(AS(buf, r + 8, k8 + lk    ));
                a[i][2] = to_tf32_u(AS(buf, r    , k8 + lk + 4));
                a[i][3] = to_tf32_u(AS(buf, r + 8, k8 + lk + 4));
            }
            #pragma unroll
            for (int j = 0; j < 2; j++) {
                int cn = warpN * 16 + j * 8 + lm;
                b[j][0] = to_tf32_u(BS(buf, k8 + lk    , cn));
                b[j][1] = to_tf32_u(BS(buf, k8 + lk + 4, cn));
            }
            #pragma unroll
            for (int i = 0; i < 2; i++)
                #pragma unroll
                for (int j = 0; j < 2; j++) {
                    asm volatile(
                        "mma.sync.aligned.m16n8k8.row.col.f32.tf32.tf32.f32 "
                        "{%0,%1,%2,%3}, {%4,%5,%6,%7}, {%8,%9}, {%0,%1,%2,%3};"
                        : "+f"(c[i][j][0]), "+f"(c[i][j][1]),
                          "+f"(c[i][j][2]), "+f"(c[i][j][3])
                        : "r"(a[i][0]), "r"(a[i][1]), "r"(a[i][2]), "r"(a[i][3]),
                          "r"(b[j][0]), "r"(b[j][1]));
                }
        }
        __syncthreads();
    }

    #pragma unroll
    for (int i = 0; i < 2; i++) {
        #pragma unroll
        for (int j = 0; j < 2; j++) {
            int r  = m0 + warpM * 32 + i * 16 + lm;
            int cn = n0 + warpN * 16 + j * 8 + 2 * lk;
            float b0 = bias[cn], b1 = bias[cn + 1];
            #pragma unroll
            for (int half = 0; half < 2; half++) {
                int rr = r + half * 8;
                float v0 = c[i][j][half * 2 + 0] + b0;
                float v1 = c[i][j][half * 2 + 1] + b1;
                if (mode == 1) {
                    v0 += resid[(size_t)rr * N + cn];
                    v1 += resid[(size_t)rr * N + cn + 1];
                } else if (mode == 2) {
                    v0 = 0.5f * v0 * (1.0f + erff(v0 * 0.70710678118654752f));
                    v1 = 0.5f * v1 * (1.0f + erff(v1 * 0.70710678118654752f));
                }
                *(float2*)&C[(size_t)rr * N + cn] = make_float2(v0, v1);
            }
        }
    }
    #undef AS
    #undef BS
}

__global__ __launch_bounds__(256)
void gemm_tf32(const float* __restrict__ A, const float* __restrict__ B,
               const float* __restrict__ bias, const float* __restrict__ resid,
               float* __restrict__ C, int K, int N, int mode) {
    gemm_core(A, B, bias, resid, C, K, N, mode,
              blockIdx.y * GTM, blockIdx.x * GTN);
}

// fused QKV: blockIdx.z selects weight/bias/output
__global__ __launch_bounds__(256)
void gemm_qkv(const float* __restrict__ A,
              const float* __restrict__ Wq, const float* __restrict__ bq,
              const float* __restrict__ Wk, const float* __restrict__ bk,
              const float* __restrict__ Wv, const float* __restrict__ bv,
              float* __restrict__ Q, float* __restrict__ K,
              float* __restrict__ V) {
    int z = blockIdx.z;
    const float* B    = (z == 0) ? Wq : (z == 1) ? Wk : Wv;
    const float* bias = (z == 0) ? bq : (z == 1) ? bk : bv;
    float*       C    = (z == 0) ? Q  : (z == 1) ? K  : V;
    gemm_core(A, B, bias, nullptr, C, CC, CC, 0,
              blockIdx.y * GTM, blockIdx.x * GTN);
}

// ---------------- fused single-pass edge attention (+probe k=3 inline) ------
__global__ __launch_bounds__(256)
void attn_kernel(const float* __restrict__ spde,
                 const float* __restrict__ etb) {
    int d = blockIdx.x;
    int t = threadIdx.x, h = t >> 5;
    int beg = g_off[d], end = g_off[d + 1];
    float q  = g_Q[d*CC + t];
    float et = etb[0];
    float sum = 0.0f, acc = 0.0f;
    for (int i = beg; i < end; i++) {
        int pk = g_elist[i];
        int e = pk & 0x1FFFF;
        int s = pk >> 17;
        float kv = g_K[s*CC + t];
        float p = q * kv;
        #pragma unroll
        for (int o = 16; o; o >>= 1) p += __shfl_xor_sync(0xffffffffu, p, o);
        int sp = G_SPD[e];
        if (sp == 0)   // probe k=3 inline against F3; else unreachable -> 4
            sp = ((g_F3[s*FW + (d >> 5)] >> (d & 31)) & 1u) ? 3 : 4;
        float ex = expf(p * 0.17677669529663687f + spde[sp*HH + h] + et);
        sum += ex;
        acc += ex * g_V[s*CC + t];
    }
    float inv = (sum > 0.0f) ? (1.0f / sum) : 0.0f;
    g_msg[d*CC + t] = acc * inv;
}

// ---------------- launch ----------------------------------------------------
extern "C" void kernel_launch(void* const* d_in, const int* in_sizes, int n_in,
                              void* d_out, int out_size) {
    const float* x      = (const float*)d_in[0];
    const int*   ei     = (const int*)  d_in[1];
    const float* Wq     = (const float*)d_in[2];
    const float* bq     = (const float*)d_in[3];
    const float* Wk     = (const float*)d_in[4];
    const float* bk     = (const float*)d_in[5];
    const float* Wv     = (const float*)d_in[6];
    const float* bv     = (const float*)d_in[7];
    const float* Wo     = (const float*)d_in[8];
    const float* bo     = (const float*)d_in[9];
    const float* W1     = (const float*)d_in[10];
    const float* b1     = (const float*)d_in[11];
    const float* W2     = (const float*)d_in[12];
    const float* b2     = (const float*)d_in[13];
    const float* g1     = (const float*)d_in[14];
    const float* beta1  = (const float*)d_in[15];
    const float* g2     = (const float*)d_in[16];
    const float* beta2  = (const float*)d_in[17];
    const float* spde   = (const float*)d_in[18];
    const float* ide    = (const float*)d_in[19];
    const float* ode    = (const float*)d_in[20];
    const float* etb    = (const float*)d_in[21];
    float* out = (float*)d_out;

    void* p_zblk;
    unsigned *pF2, *pF3;
    float *pQ, *pK, *pV, *p_xn, *p_xin, *p_msgf, *p_h, *p_hn, *p_ff1;
    cudaGetSymbolAddress(&p_zblk, g_zblk);
    cudaGetSymbolAddress((void**)&pF2,   g_F2);
    cudaGetSymbolAddress((void**)&pF3,   g_F3);
    cudaGetSymbolAddress((void**)&pQ,    g_Q);
    cudaGetSymbolAddress((void**)&pK,    g_K);
    cudaGetSymbolAddress((void**)&pV,    g_V);
    cudaGetSymbolAddress((void**)&p_xin, g_xin);
    cudaGetSymbolAddress((void**)&p_xn,  g_xn);
    cudaGetSymbolAddress((void**)&p_msgf,g_msg);
    cudaGetSymbolAddress((void**)&p_h,   g_h);
    cudaGetSymbolAddress((void**)&p_hn,  g_hn);
    cudaGetSymbolAddress((void**)&p_ff1, g_ff1);

    unsigned* F1 = (unsigned*)p_zblk + OFF_F1;

    // one-time resource init (same work every call; no behavioral branching)
    static cudaStream_t s1;
    static cudaEvent_t  ev1, ev2;
    static int init_done = 0;
    if (!init_done) {
        cudaFuncSetAttribute(gemm_tf32, cudaFuncAttributeMaxDynamicSharedMemorySize, GSMEM);
        cudaFuncSetAttribute(gemm_qkv,  cudaFuncAttributeMaxDynamicSharedMemorySize, GSMEM);
        cudaStreamCreateWithFlags(&s1, cudaStreamNonBlocking);
        cudaEventCreateWithFlags(&ev1, cudaEventDisableTiming);
        cudaEventCreateWithFlags(&ev2, cudaEventDisableTiming);
        init_done = 1;
    }

    // ---- s0 (capture stream): reset + degrees/step-1 ----
    cudaMemsetAsync(p_zblk, 0, (size_t)ZTOT * sizeof(unsigned));
    deg_prop1_kernel<<<EE/256, 256>>>(ei);
    cudaEventRecord(ev1, 0);

    // ---- s1 branch: CSR build + SPD propagation (independent of dense path)
    cudaStreamWaitEvent(s1, ev1, 0);
    scan_kernel<<<1, 1024, 0, s1>>>();
    fill_kernel<<<EE/256, 256, 0, s1>>>(ei);
    prop_gather_kernel<<<NN/4, 128, 0, s1>>>(F1, pF2, 1);
    prop_gather_kernel<<<NN/4, 128, 0, s1>>>(pF2, pF3, 2);
    cudaEventRecord(ev2, s1);

    // ---- s0 branch: xin+LN1 and QKV GEMM (needs only degrees) ----
    xin_ln_kernel<<<NN, CC>>>(x, ide, ode, g1, beta1);
    dim3 blk(256);
    dim3 grdQKV(CC/GTN, NN/GTM, 3);  // 4 x 64 x 3
    gemm_qkv<<<grdQKV, blk, GSMEM>>>(p_xn, Wq, bq, Wk, bk, Wv, bv, pQ, pK, pV);

    // ---- join: attention needs QKV (s0) + CSR/SPD (s1) ----
    cudaStreamWaitEvent(0, ev2, 0);
    attn_kernel<<<NN, 256>>>(spde, etb);

    // h = x_in + msg @ Wo + bo
    dim3 grdC(CC/GTN, NN/GTM);       // 4 x 64
    gemm_tf32<<<grdC, blk, GSMEM>>>(p_msgf, Wo, bo, p_xin, p_h, CC, CC, 1);

    // LN2 + FFN
    ln_kernel<<<NN, CC>>>(p_h, g2, beta2, p_hn);
    dim3 grdF1(C4/GTN, NN/GTM);      // 16 x 64
    gemm_tf32<<<grdF1, blk, GSMEM>>>(p_hn, W1, b1, nullptr, p_ff1, CC, C4, 2);
    gemm_tf32<<<grdC,  blk, GSMEM>>>(p_ff1, W2, b2, p_h, out, C4, CC, 1);
}